// round 4
// baseline (speedup 1.0000x reference)
#include <cuda_runtime.h>
#include <math.h>

#define TT   512
#define BB   64
#define II   1024
#define HH   1024
#define G4   4096      // 4*H
#define GRID 128       // persistent CTAs (<= 148 SMs, all co-resident)

typedef unsigned long long ull;

// Scratch: x_gates [T, B, 4H] fp32 (static device array; no runtime alloc)
__device__ float g_xg[(size_t)TT * BB * G4];
__device__ unsigned g_bar;

__device__ __forceinline__ ull pack2(float x) {
    ull r; asm("mov.b64 %0, {%1,%1};" : "=l"(r) : "f"(x)); return r;
}
__device__ __forceinline__ void fma2(ull& d, ull a, ull b) {
    asm("fma.rn.f32x2 %0, %1, %2, %3;" : "=l"(d) : "l"(a), "l"(b), "l"(d));
}
__device__ __forceinline__ float2 unpack2(ull v) {
    float2 r; asm("mov.b64 {%0,%1}, %2;" : "=f"(r.x), "=f"(r.y) : "l"(v)); return r;
}

// ---------------------------------------------------------------------------
// Phase 1: x_gates = input @ w_ih^T + b_ih + b_hh
// ---------------------------------------------------------------------------
__global__ __launch_bounds__(256)
void gemm_xgates(const float* __restrict__ A, const float* __restrict__ W,
                 const float* __restrict__ bih, const float* __restrict__ bhh,
                 float* __restrict__ C)
{
    __shared__ float As[16][64];
    __shared__ float Bs[16][64];

    const int tx = threadIdx.x, ty = threadIdx.y;
    const int tid = ty * 16 + tx;
    const int m0 = blockIdx.y * 64;
    const int n0 = blockIdx.x * 64;
    const int lr = tid >> 2;
    const int lc = tid & 3;

    const float* Arow = A + (size_t)(m0 + lr) * II + lc * 4;
    const float* Wrow = W + (size_t)(n0 + lr) * II + lc * 4;

    float acc[4][4] = {};

    for (int k0 = 0; k0 < II; k0 += 16) {
        float4 av = *(const float4*)(Arow + k0);
        float4 bv = *(const float4*)(Wrow + k0);
        As[lc * 4 + 0][lr] = av.x; As[lc * 4 + 1][lr] = av.y;
        As[lc * 4 + 2][lr] = av.z; As[lc * 4 + 3][lr] = av.w;
        Bs[lc * 4 + 0][lr] = bv.x; Bs[lc * 4 + 1][lr] = bv.y;
        Bs[lc * 4 + 2][lr] = bv.z; Bs[lc * 4 + 3][lr] = bv.w;
        __syncthreads();
        #pragma unroll
        for (int kk = 0; kk < 16; kk++) {
            float4 a = *(const float4*)&As[kk][ty * 4];
            float4 b = *(const float4*)&Bs[kk][tx * 4];
            acc[0][0] += a.x * b.x; acc[0][1] += a.x * b.y; acc[0][2] += a.x * b.z; acc[0][3] += a.x * b.w;
            acc[1][0] += a.y * b.x; acc[1][1] += a.y * b.y; acc[1][2] += a.y * b.z; acc[1][3] += a.y * b.w;
            acc[2][0] += a.z * b.x; acc[2][1] += a.z * b.y; acc[2][2] += a.z * b.z; acc[2][3] += a.z * b.w;
            acc[3][0] += a.w * b.x; acc[3][1] += a.w * b.y; acc[3][2] += a.w * b.z; acc[3][3] += a.w * b.w;
        }
        __syncthreads();
    }

    #pragma unroll
    for (int i = 0; i < 4; i++) {
        const int m = m0 + ty * 4 + i;
        #pragma unroll
        for (int j = 0; j < 4; j++) {
            const int n = n0 + tx * 4 + j;
            C[(size_t)m * G4 + n] = acc[i][j] + bih[n] + bhh[n];
        }
    }
}

// ---------------------------------------------------------------------------
__global__ void bar_reset() { g_bar = 0; }

// ---------------------------------------------------------------------------
// Persistent recurrence kernel: 128 CTAs x 256 threads run all 512 steps.
// CTA nb owns h-cols [nb*8, nb*8+8) -> 32 gate rows; its W slice (128 KB)
// stays in SMEM. Split-K by 2 (two 128-thread groups), 4x4 microtile with
// fma.rn.f32x2. Register-prefetch pipeline hides L2/DRAM staging latency
// under the fma loop. c lives in SMEM. Grid sync via atomic counter.
// ---------------------------------------------------------------------------
#define WS_OFF 0
#define HS_OFF 32768
#define HS_G   (64 * 68)
#define GP_OFF (HS_OFF + 2 * HS_G)
#define GB_OFF (GP_OFF + 64 * 33)
#define CS_OFF (GB_OFF + 64 * 33)
#define SMEM_FLOATS (CS_OFF + 512)

__global__ __launch_bounds__(256, 1)
void lstm_persist(const float* __restrict__ xg,   // [T, B, 4H]
                  const float* h0, const float* c0,
                  const float* __restrict__ Whh,  // [4H, H]
                  float* out,                      // [T, B, H]
                  float* hf, float* cf)            // [B, H] each
{
    extern __shared__ float sm[];
    float* Ws = sm + WS_OFF;
    float* Hs = sm + HS_OFF;
    float* Gp = sm + GP_OFF;
    float* Gb = sm + GB_OFF;
    float* Cs = sm + CS_OFF;

    const int tid = threadIdx.x;
    const int nb  = blockIdx.x;            // 0..127

    // ---- load W slice: 32 gate rows x 1024 k, into Ws[k][col] ----
    {
        const int col   = tid >> 3;        // 0..31
        const int lane8 = tid & 7;         // 0..7
        const int grow  = (col >> 3) * HH + nb * 8 + (col & 7);
        const float* wr = Whh + (size_t)grow * HH;
        for (int kb = 0; kb < II; kb += 32) {
            const int k = kb + lane8 * 4;
            float4 v = *(const float4*)(wr + k);
            Ws[(k + 0) * 32 + col] = v.x;
            Ws[(k + 1) * 32 + col] = v.y;
            Ws[(k + 2) * 32 + col] = v.z;
            Ws[(k + 3) * 32 + col] = v.w;
        }
    }
    // ---- load c0 slice into Cs ----
    #pragma unroll
    for (int r = 0; r < 2; r++) {
        const int e = tid + r * 256;
        const int b = e >> 3, j = e & 7;
        Cs[e] = c0[(size_t)b * HH + nb * 8 + j];
    }
    __syncthreads();

    const int grp = tid >> 7;              // split-K group (0/1)
    const int t7  = tid & 127;
    const int tx  = t7 & 7;                // cols tx*4..tx*4+3
    const int ty  = t7 >> 3;               // batches ty*4..ty*4+3
    float* hsg = Hs + grp * HS_G;

    // staging address components (fixed per thread)
    int st_b[8], st_g[8], st_kq[8];
    #pragma unroll
    for (int r = 0; r < 8; r++) {
        const int id = tid + r * 256;
        st_b[r]  = id >> 5;
        st_g[r]  = (id & 31) >> 4;
        st_kq[r] = id & 15;
    }

    for (int t = 0; t < TT; t++) {
        const float* h_in = (t == 0) ? h0 : out + (size_t)(t - 1) * BB * HH;
        const float* xgt  = xg + (size_t)t * BB * G4;
        float* out_t      = out + (size_t)t * BB * HH;

        // ---- prefetch this step's xg slice (DRAM latency hidden) ----
        float4 xv[4];
        if (grp == 0) {
            const int sect = tx >> 1;
            const int jj0  = (tx & 1) * 4;
            #pragma unroll
            for (int i = 0; i < 4; i++)
                xv[i] = __ldg((const float4*)(xgt + (size_t)(ty * 4 + i) * G4
                              + sect * HH + nb * 8 + jj0));
        }

        // ---- prefetch chunk 0 of h ----
        float4 pv[8];
        #pragma unroll
        for (int r = 0; r < 8; r++)
            pv[r] = __ldcg((const float4*)(h_in + (size_t)st_b[r] * HH
                           + st_g[r] * 512 + st_kq[r] * 4));

        ull acc[4][2];
        #pragma unroll
        for (int i = 0; i < 4; i++) { acc[i][0] = 0ull; acc[i][1] = 0ull; }

        for (int ch = 0; ch < 8; ch++) {
            // store prefetched chunk into Hs (bank-rotated scatter)
            #pragma unroll
            for (int r = 0; r < 8; r++) {
                float vv[4] = {pv[r].x, pv[r].y, pv[r].z, pv[r].w};
                float* hd = Hs + st_g[r] * HS_G;
                #pragma unroll
                for (int jj = 0; jj < 4; jj++) {
                    const int e = (jj + st_kq[r]) & 3;
                    hd[(st_kq[r] * 4 + e) * 68 + st_b[r]] = vv[e];
                }
            }
            __syncthreads();

            // prefetch next chunk (overlaps the fma loop below)
            if (ch < 7) {
                #pragma unroll
                for (int r = 0; r < 8; r++)
                    pv[r] = __ldcg((const float4*)(h_in + (size_t)st_b[r] * HH
                                   + st_g[r] * 512 + (ch + 1) * 64 + st_kq[r] * 4));
            }

            const int kbase = grp * 512 + ch * 64;
            #pragma unroll 4
            for (int kk = 0; kk < 64; kk++) {
                const float4 hv = *(const float4*)&hsg[kk * 68 + ty * 4];
                const ulonglong2 wv = *(const ulonglong2*)&Ws[(kbase + kk) * 32 + tx * 4];
                const ull a0 = pack2(hv.x), a1 = pack2(hv.y);
                const ull a2 = pack2(hv.z), a3 = pack2(hv.w);
                fma2(acc[0][0], a0, wv.x); fma2(acc[0][1], a0, wv.y);
                fma2(acc[1][0], a1, wv.x); fma2(acc[1][1], a1, wv.y);
                fma2(acc[2][0], a2, wv.x); fma2(acc[2][1], a2, wv.y);
                fma2(acc[3][0], a3, wv.x); fma2(acc[3][1], a3, wv.y);
            }
            __syncthreads();
        }

        // ---- split-K reduction ----
        if (grp == 1) {
            #pragma unroll
            for (int i = 0; i < 4; i++) {
                const int b = ty * 4 + i;
                float2 p0 = unpack2(acc[i][0]);
                float2 p1 = unpack2(acc[i][1]);
                Gp[b * 33 + tx * 4 + 0] = p0.x;
                Gp[b * 33 + tx * 4 + 1] = p0.y;
                Gp[b * 33 + tx * 4 + 2] = p1.x;
                Gp[b * 33 + tx * 4 + 3] = p1.y;
            }
        }
        __syncthreads();
        if (grp == 0) {
            #pragma unroll
            for (int i = 0; i < 4; i++) {
                const int b = ty * 4 + i;
                float2 p0 = unpack2(acc[i][0]);
                float2 p1 = unpack2(acc[i][1]);
                Gb[b * 33 + tx * 4 + 0] = p0.x + Gp[b * 33 + tx * 4 + 0] + xv[i].x;
                Gb[b * 33 + tx * 4 + 1] = p0.y + Gp[b * 33 + tx * 4 + 1] + xv[i].y;
                Gb[b * 33 + tx * 4 + 2] = p1.x + Gp[b * 33 + tx * 4 + 2] + xv[i].z;
                Gb[b * 33 + tx * 4 + 3] = p1.y + Gp[b * 33 + tx * 4 + 3] + xv[i].w;
            }
        }
        __syncthreads();

        // ---- fused pointwise LSTM update ----
        #pragma unroll
        for (int r = 0; r < 2; r++) {
            const int e = tid + r * 256;
            const int b = e >> 3, j = e & 7;
            const float ig = Gb[b * 33 + j];
            const float fg = Gb[b * 33 + 8 + j];
            const float gg = Gb[b * 33 + 16 + j];
            const float og = Gb[b * 33 + 24 + j];
            const float si = 1.0f / (1.0f + expf(-ig));
            const float sf = 1.0f / (1.0f + expf(-fg));
            const float so = 1.0f / (1.0f + expf(-og));
            const float tg = tanhf(gg);
            const float cn = sf * Cs[e] + si * tg;
            const float hn = so * tanhf(cn);
            Cs[e] = cn;
            const int hc = nb * 8 + j;
            __stcg(out_t + (size_t)b * HH + hc, hn);
            if (t == TT - 1) {
                hf[(size_t)b * HH + hc] = hn;
                cf[(size_t)b * HH + hc] = cn;
            }
        }

        // ---- grid-wide barrier ----
        __syncthreads();
        if (tid == 0) {
            __threadfence();
            const unsigned target = (unsigned)(t + 1) * GRID;
            atomicAdd(&g_bar, 1u);
            while (*(volatile unsigned*)&g_bar < target) { __nanosleep(64); }
            __threadfence();
        }
        __syncthreads();
    }
}

// ---------------------------------------------------------------------------
extern "C" void kernel_launch(void* const* d_in, const int* in_sizes, int n_in,
                              void* d_out, int out_size)
{
    const float* input = (const float*)d_in[0];
    const float* h0    = (const float*)d_in[1];
    const float* c0    = (const float*)d_in[2];
    const float* w_ih  = (const float*)d_in[3];
    const float* w_hh  = (const float*)d_in[4];
    const float* b_ih  = (const float*)d_in[5];
    const float* b_hh  = (const float*)d_in[6];

    float* outputs = (float*)d_out;                 // [T, B, H]
    float* hf = outputs + (size_t)TT * BB * HH;
    float* cf = hf + (size_t)BB * HH;

    float* xg = nullptr;
    cudaGetSymbolAddress((void**)&xg, g_xg);

    const size_t smem_bytes = (size_t)SMEM_FLOATS * sizeof(float);
    cudaFuncSetAttribute(lstm_persist,
                         cudaFuncAttributeMaxDynamicSharedMemorySize,
                         (int)smem_bytes);

    bar_reset<<<1, 1>>>();

    dim3 blk(16, 16);
    gemm_xgates<<<dim3(G4 / 64, (TT * BB) / 64), blk>>>(input, w_ih, b_ih, b_hh, xg);

    lstm_persist<<<GRID, 256, smem_bytes>>>(xg, h0, c0, w_hh, outputs, hf, cf);
}

// round 5
// speedup vs baseline: 1.3215x; 1.3215x over previous
#include <cuda_runtime.h>
#include <math.h>
#include <stdint.h>

#define TT   512
#define BB   64
#define II   1024
#define HH   1024
#define G4   4096      // 4*H
#define GRID 128       // persistent CTAs (<= 148 SMs, all co-resident)

typedef unsigned long long ull;

// Scratch (static device arrays; no runtime alloc)
__device__ float g_xg[(size_t)TT * BB * G4];   // x_gates [T, B, 4H]
__device__ float g_hT[2][HH * BB];             // transposed h ping-pong [h][b]
__device__ unsigned g_bar;

__device__ __forceinline__ ull pack2(float x) {
    ull r; asm("mov.b64 %0, {%1,%1};" : "=l"(r) : "f"(x)); return r;
}
__device__ __forceinline__ void fma2(ull& d, ull a, ull b) {
    asm("fma.rn.f32x2 %0, %1, %2, %3;" : "=l"(d) : "l"(a), "l"(b), "l"(d));
}
__device__ __forceinline__ float2 unpack2(ull v) {
    float2 r; asm("mov.b64 {%0,%1}, %2;" : "=f"(r.x), "=f"(r.y) : "l"(v)); return r;
}
__device__ __forceinline__ void cp16(uint32_t dst_smem, const void* src) {
    asm volatile("cp.async.cg.shared.global [%0], [%1], 16;"
                 :: "r"(dst_smem), "l"(src));
}

// ---------------------------------------------------------------------------
// Phase 1: x_gates = input @ w_ih^T + b_ih + b_hh.  fma.rn.f32x2 inner:
// m-pairs packed directly from m-contiguous As tile (no movs for A).
// ---------------------------------------------------------------------------
__global__ __launch_bounds__(256)
void gemm_xgates(const float* __restrict__ A, const float* __restrict__ W,
                 const float* __restrict__ bih, const float* __restrict__ bhh,
                 float* __restrict__ C)
{
    __shared__ float As[16][64];   // [k][m]
    __shared__ float Bs[16][64];   // [k][n]

    const int tx = threadIdx.x, ty = threadIdx.y;     // 16 x 16
    const int tid = ty * 16 + tx;
    const int m0 = blockIdx.y * 64;
    const int n0 = blockIdx.x * 64;
    const int lr = tid >> 2;
    const int lc = tid & 3;

    const float* Arow = A + (size_t)(m0 + lr) * II + lc * 4;
    const float* Wrow = W + (size_t)(n0 + lr) * II + lc * 4;

    ull acc[2][4];                 // [m-pair][n], each ull = (m, m+1)
    #pragma unroll
    for (int i = 0; i < 2; i++)
        #pragma unroll
        for (int j = 0; j < 4; j++) acc[i][j] = 0ull;

    for (int k0 = 0; k0 < II; k0 += 16) {
        float4 av = *(const float4*)(Arow + k0);
        float4 bv = *(const float4*)(Wrow + k0);
        As[lc * 4 + 0][lr] = av.x; As[lc * 4 + 1][lr] = av.y;
        As[lc * 4 + 2][lr] = av.z; As[lc * 4 + 3][lr] = av.w;
        Bs[lc * 4 + 0][lr] = bv.x; Bs[lc * 4 + 1][lr] = bv.y;
        Bs[lc * 4 + 2][lr] = bv.z; Bs[lc * 4 + 3][lr] = bv.w;
        __syncthreads();
        #pragma unroll
        for (int kk = 0; kk < 16; kk++) {
            const ulonglong2 am = *(const ulonglong2*)&As[kk][ty * 4];
            const float4 b = *(const float4*)&Bs[kk][tx * 4];
            const ull b0 = pack2(b.x), b1 = pack2(b.y);
            const ull b2 = pack2(b.z), b3 = pack2(b.w);
            fma2(acc[0][0], am.x, b0); fma2(acc[0][1], am.x, b1);
            fma2(acc[0][2], am.x, b2); fma2(acc[0][3], am.x, b3);
            fma2(acc[1][0], am.y, b0); fma2(acc[1][1], am.y, b1);
            fma2(acc[1][2], am.y, b2); fma2(acc[1][3], am.y, b3);
        }
        __syncthreads();
    }

    #pragma unroll
    for (int i = 0; i < 2; i++) {
        #pragma unroll
        for (int j = 0; j < 4; j++) {
            const int n = n0 + tx * 4 + j;
            const float bb = bih[n] + bhh[n];
            const float2 p = unpack2(acc[i][j]);
            const int m = m0 + ty * 4 + i * 2;
            C[(size_t)m * G4 + n]       = p.x + bb;
            C[(size_t)(m + 1) * G4 + n] = p.y + bb;
        }
    }
}

// ---------------------------------------------------------------------------
// prep: transpose h0 -> g_hT[0] ([h][b]) and reset the grid barrier.
// ---------------------------------------------------------------------------
__global__ __launch_bounds__(256)
void prep(const float* __restrict__ h0)
{
    const int idx = blockIdx.x * 256 + threadIdx.x;   // 0..65535
    const int h = idx >> 6, b = idx & 63;
    g_hT[0][h * 64 + b] = h0[(size_t)b * HH + h];
    if (idx == 0) g_bar = 0;
}

// ---------------------------------------------------------------------------
// Persistent recurrence: 128 CTAs x 256 threads, all 512 steps.
// CTA nb owns h-cols [nb*8,nb*8+8) -> 32 gate rows; W slice (128 KB) in SMEM.
// Split-K by 2; 4x4 microtile with fma.rn.f32x2. h staged from transposed
// global scratch via double-buffered cp.async (no transposition, no local
// memory). c in SMEM. Grid sync via atomic counter (reset by prep).
//
// SMEM floats:
//   Ws   [1024][32]                        : 32768
//   Hb   [2 stage][2 grp][64 k][64 b]      : 16384
//   Gp   [64][33]                          : 2112
//   Gb   [64][33]                          : 2112
//   Cs   [512]                             : 512
// total 53888 floats = 215552 B
// ---------------------------------------------------------------------------
#define WS_OFF 0
#define HB_OFF 32768
#define HB_STG 8192
#define GP_OFF (HB_OFF + 2 * HB_STG)
#define GB_OFF (GP_OFF + 64 * 33)
#define CS_OFF (GB_OFF + 64 * 33)
#define SMEM_FLOATS (CS_OFF + 512)

__global__ __launch_bounds__(256, 1)
void lstm_persist(const float* __restrict__ xg,   // [T, B, 4H]
                  const float* c0,
                  const float* __restrict__ Whh,  // [4H, H]
                  float* out,                      // [T, B, H]
                  float* hf, float* cf)            // [B, H] each
{
    extern __shared__ float sm[];
    float* Ws = sm + WS_OFF;
    float* Gp = sm + GP_OFF;
    float* Gb = sm + GB_OFF;
    float* Cs = sm + CS_OFF;
    const uint32_t sbase   = (uint32_t)__cvta_generic_to_shared(sm);
    const uint32_t hb_base = sbase + HB_OFF * 4;

    const int tid = threadIdx.x;
    const int nb  = blockIdx.x;            // 0..127

    // ---- load W slice: 32 gate rows x 1024 k -> Ws[k][col] ----
    {
        const int col   = tid >> 3;
        const int lane8 = tid & 7;
        const int grow  = (col >> 3) * HH + nb * 8 + (col & 7);
        const float* wr = Whh + (size_t)grow * HH;
        for (int kb = 0; kb < II; kb += 32) {
            const int k = kb + lane8 * 4;
            float4 v = *(const float4*)(wr + k);
            Ws[(k + 0) * 32 + col] = v.x;
            Ws[(k + 1) * 32 + col] = v.y;
            Ws[(k + 2) * 32 + col] = v.z;
            Ws[(k + 3) * 32 + col] = v.w;
        }
    }
    #pragma unroll
    for (int r = 0; r < 2; r++) {
        const int e = tid + r * 256;
        const int b = e >> 3, j = e & 7;
        Cs[e] = c0[(size_t)b * HH + nb * 8 + j];
    }
    __syncthreads();

    const int grp = tid >> 7;              // split-K group (0/1)
    const int t7  = tid & 127;
    const int tx  = t7 & 7;                // cols tx*4..+3 (local 0..31)
    const int ty  = t7 >> 3;               // batches ty*4..+3

    // per-thread staging offsets (8 cp.asyncs/chunk, fully static unroll)
    int  src_off[8];                       // float offset into g_hT (ch=0)
    uint32_t dst_off[8];                   // byte offset into stage 0
    #pragma unroll
    for (int r = 0; r < 8; r++) {
        const int id = tid + r * 256;      // 0..2047 float4s
        const int g  = id >> 10;
        const int kk = (id >> 4) & 63;
        const int b4 = id & 15;
        src_off[r] = (g * 512 + kk) * 64 + b4 * 4;
        dst_off[r] = (uint32_t)((g * 4096 + kk * 64 + b4 * 4) * 4);
    }

    for (int t = 0; t < TT; t++) {
        const float* hT_cur = g_hT[t & 1];
        float*       hT_nxt = g_hT[(t + 1) & 1];
        const float* xgt    = xg + (size_t)t * BB * G4;
        float*       out_t  = out + (size_t)t * BB * HH;

        // ---- prefetch this step's xg slice ----
        float4 xv[4];
        if (grp == 0) {
            const int sect = tx >> 1;
            const int jj0  = (tx & 1) * 4;
            #pragma unroll
            for (int i = 0; i < 4; i++)
                xv[i] = __ldg((const float4*)(xgt + (size_t)(ty * 4 + i) * G4
                              + sect * HH + nb * 8 + jj0));
        }

        // ---- prologue: stage chunk 0 into stage buffer 0 ----
        #pragma unroll
        for (int r = 0; r < 8; r++)
            cp16(hb_base + dst_off[r], hT_cur + src_off[r]);
        asm volatile("cp.async.commit_group;");

        ull acc[4][2];
        #pragma unroll
        for (int i = 0; i < 4; i++) { acc[i][0] = 0ull; acc[i][1] = 0ull; }

        for (int ch = 0; ch < 8; ch++) {
            if (ch < 7) {
                const uint32_t db = hb_base + ((ch + 1) & 1) * (HB_STG * 4);
                const float* sb = hT_cur + (ch + 1) * 4096;
                #pragma unroll
                for (int r = 0; r < 8; r++)
                    cp16(db + dst_off[r], sb + src_off[r]);
                asm volatile("cp.async.commit_group;");
                asm volatile("cp.async.wait_group 1;");
            } else {
                asm volatile("cp.async.wait_group 0;");
            }
            __syncthreads();

            const float* hsg = sm + HB_OFF + (ch & 1) * HB_STG + grp * 4096;
            const int kbase = grp * 512 + ch * 64;
            #pragma unroll 4
            for (int kk = 0; kk < 64; kk++) {
                const float4 hv = *(const float4*)&hsg[kk * 64 + ty * 4];
                const ulonglong2 wv = *(const ulonglong2*)&Ws[(kbase + kk) * 32 + tx * 4];
                const ull a0 = pack2(hv.x), a1 = pack2(hv.y);
                const ull a2 = pack2(hv.z), a3 = pack2(hv.w);
                fma2(acc[0][0], a0, wv.x); fma2(acc[0][1], a0, wv.y);
                fma2(acc[1][0], a1, wv.x); fma2(acc[1][1], a1, wv.y);
                fma2(acc[2][0], a2, wv.x); fma2(acc[2][1], a2, wv.y);
                fma2(acc[3][0], a3, wv.x); fma2(acc[3][1], a3, wv.y);
            }
            __syncthreads();
        }

        // ---- split-K reduction ----
        if (grp == 1) {
            #pragma unroll
            for (int i = 0; i < 4; i++) {
                const int b = ty * 4 + i;
                float2 p0 = unpack2(acc[i][0]);
                float2 p1 = unpack2(acc[i][1]);
                Gp[b * 33 + tx * 4 + 0] = p0.x;
                Gp[b * 33 + tx * 4 + 1] = p0.y;
                Gp[b * 33 + tx * 4 + 2] = p1.x;
                Gp[b * 33 + tx * 4 + 3] = p1.y;
            }
        }
        __syncthreads();
        if (grp == 0) {
            #pragma unroll
            for (int i = 0; i < 4; i++) {
                const int b = ty * 4 + i;
                float2 p0 = unpack2(acc[i][0]);
                float2 p1 = unpack2(acc[i][1]);
                Gb[b * 33 + tx * 4 + 0] = p0.x + Gp[b * 33 + tx * 4 + 0] + xv[i].x;
                Gb[b * 33 + tx * 4 + 1] = p0.y + Gp[b * 33 + tx * 4 + 1] + xv[i].y;
                Gb[b * 33 + tx * 4 + 2] = p1.x + Gp[b * 33 + tx * 4 + 2] + xv[i].z;
                Gb[b * 33 + tx * 4 + 3] = p1.y + Gp[b * 33 + tx * 4 + 3] + xv[i].w;
            }
        }
        __syncthreads();

        // ---- fused pointwise LSTM update ----
        #pragma unroll
        for (int r = 0; r < 2; r++) {
            const int e = tid + r * 256;
            const int b = e >> 3, j = e & 7;
            const float ig = Gb[b * 33 + j];
            const float fg = Gb[b * 33 + 8 + j];
            const float gg = Gb[b * 33 + 16 + j];
            const float og = Gb[b * 33 + 24 + j];
            const float si = 1.0f / (1.0f + expf(-ig));
            const float sf = 1.0f / (1.0f + expf(-fg));
            const float so = 1.0f / (1.0f + expf(-og));
            const float tg = tanhf(gg);
            const float cn = sf * Cs[e] + si * tg;
            const float hn = so * tanhf(cn);
            Cs[e] = cn;
            const int hc = nb * 8 + j;
            __stcg(out_t + (size_t)b * HH + hc, hn);
            __stcg(hT_nxt + hc * 64 + b, hn);
            if (t == TT - 1) {
                hf[(size_t)b * HH + hc] = hn;
                cf[(size_t)b * HH + hc] = cn;
            }
        }

        // ---- grid-wide barrier ----
        __syncthreads();
        if (tid == 0) {
            __threadfence();
            const unsigned target = (unsigned)(t + 1) * GRID;
            atomicAdd(&g_bar, 1u);
            while (*(volatile unsigned*)&g_bar < target) { }
            __threadfence();
        }
        __syncthreads();
    }
}

// ---------------------------------------------------------------------------
extern "C" void kernel_launch(void* const* d_in, const int* in_sizes, int n_in,
                              void* d_out, int out_size)
{
    const float* input = (const float*)d_in[0];
    const float* h0    = (const float*)d_in[1];
    const float* c0    = (const float*)d_in[2];
    const float* w_ih  = (const float*)d_in[3];
    const float* w_hh  = (const float*)d_in[4];
    const float* b_ih  = (const float*)d_in[5];
    const float* b_hh  = (const float*)d_in[6];

    float* outputs = (float*)d_out;                 // [T, B, H]
    float* hf = outputs + (size_t)TT * BB * HH;
    float* cf = hf + (size_t)BB * HH;

    float* xg = nullptr;
    cudaGetSymbolAddress((void**)&xg, g_xg);

    const size_t smem_bytes = (size_t)SMEM_FLOATS * sizeof(float);
    cudaFuncSetAttribute(lstm_persist,
                         cudaFuncAttributeMaxDynamicSharedMemorySize,
                         (int)smem_bytes);

    dim3 blk(16, 16);
    gemm_xgates<<<dim3(G4 / 64, (TT * BB) / 64), blk>>>(input, w_ih, b_ih, b_hh, xg);
    prep<<<256, 256>>>(h0);
    lstm_persist<<<GRID, 256, smem_bytes>>>(xg, c0, w_hh, outputs, hf, cf);
}

// round 10
// speedup vs baseline: 2.0888x; 1.5805x over previous
#include <cuda_runtime.h>
#include <math.h>
#include <stdint.h>

#define TT   512
#define BB   64
#define II   1024
#define HH   1024
#define G4   4096      // 4*H
#define GRID 128       // persistent CTAs for recurrence

typedef unsigned long long ull;

// Static device scratch (no runtime alloc)
__device__ float g_xg[(size_t)TT * BB * G4];     // x_gates [T, B, 4H]
__device__ float g_a[(size_t)TT * BB * II];      // tf32-rounded input  [32768, 1024]
__device__ float g_b[(size_t)G4 * II];           // tf32-rounded w_ih   [4096, 1024]
__device__ float g_hT[2][HH * BB];               // transposed h ping-pong [h][b]
__device__ unsigned g_bar;

__device__ __forceinline__ ull pack2(float x) {
    ull r; asm("mov.b64 %0, {%1,%1};" : "=l"(r) : "f"(x)); return r;
}
__device__ __forceinline__ void fma2(ull& d, ull a, ull b) {
    asm("fma.rn.f32x2 %0, %1, %2, %3;" : "=l"(d) : "l"(a), "l"(b), "l"(d));
}
__device__ __forceinline__ float2 unpack2(ull v) {
    float2 r; asm("mov.b64 {%0,%1}, %2;" : "=f"(r.x), "=f"(r.y) : "l"(v)); return r;
}
__device__ __forceinline__ void cp16(uint32_t dst_smem, const void* src) {
    asm volatile("cp.async.cg.shared.global [%0], [%1], 16;"
                 :: "r"(dst_smem), "l"(src));
}
__device__ __forceinline__ uint32_t rna_tf32(float x) {
    uint32_t r; asm("cvt.rna.tf32.f32 %0, %1;" : "=r"(r) : "f"(x)); return r;
}
__device__ __forceinline__ void mma_tf32(float* c, const uint32_t* a,
                                         const uint32_t* b) {
    asm("mma.sync.aligned.m16n8k8.row.col.f32.tf32.tf32.f32 "
        "{%0,%1,%2,%3}, {%4,%5,%6,%7}, {%8,%9}, {%0,%1,%2,%3};"
        : "+f"(c[0]), "+f"(c[1]), "+f"(c[2]), "+f"(c[3])
        : "r"(a[0]), "r"(a[1]), "r"(a[2]), "r"(a[3]), "r"(b[0]), "r"(b[1]));
}

// ---------------------------------------------------------------------------
// cvt pass: round input + w_ih to tf32 (rna) into g_a / g_b.
// ---------------------------------------------------------------------------
#define A_F4 8388608   // input float4 count
#define T_F4 9437184   // total float4 count
__global__ __launch_bounds__(256)
void cvt_tf32(const float* __restrict__ in, const float* __restrict__ wih)
{
    const int idx = blockIdx.x * 256 + threadIdx.x;
    const float4* src; float* dst; int i4;
    if (idx < A_F4) { src = (const float4*)in;  dst = g_a; i4 = idx; }
    else            { src = (const float4*)wih; dst = g_b; i4 = idx - A_F4; }
    float4 v = src[i4];
    uint4 o;
    o.x = rna_tf32(v.x); o.y = rna_tf32(v.y);
    o.z = rna_tf32(v.z); o.w = rna_tf32(v.w);
    *(uint4*)(dst + (size_t)i4 * 4) = o;
}

// ---------------------------------------------------------------------------
// Phase 1: tf32 mma.sync GEMM.  C[m,n] = sum_k A[m,k]*W[n,k] + bias[n]
// BM=128 x BN=128 x BK=32; 8 warps (2m x 4n), warp tile 64x32;
// double-buffered cp.async; smem rows padded to 36 floats.
// ---------------------------------------------------------------------------
#define ATILE 4608                  // 128*36 floats per stage buffer
#define GEMM_SMEM (4 * ATILE * 4)   // A0 A1 B0 B1 = 73728 bytes

__device__ __forceinline__ void stage_ab(uint32_t sb, int s, const float* ga,
                                         const float* gb_, int kb, int tid)
{
    const uint32_t ab = sb + (uint32_t)(s * ATILE) * 4;
    const uint32_t bbse = sb + (uint32_t)((2 + s) * ATILE) * 4;
    #pragma unroll
    for (int r = 0; r < 4; r++) {
        const int id = tid + r * 256;          // 0..1023
        const int row = id >> 3, k = (id & 7) * 4;
        cp16(ab + (uint32_t)(row * 36 + k) * 4,
             ga + (size_t)row * II + kb * 32 + k);
    }
    #pragma unroll
    for (int r = 0; r < 4; r++) {
        const int id = tid + r * 256;
        const int row = id >> 3, k = (id & 7) * 4;
        cp16(bbse + (uint32_t)(row * 36 + k) * 4,
             gb_ + (size_t)row * II + kb * 32 + k);
    }
    asm volatile("cp.async.commit_group;");
}

__global__ __launch_bounds__(256, 2)
void gemm_mma(const float* __restrict__ bih, const float* __restrict__ bhh,
              float* __restrict__ C)
{
    extern __shared__ float sm[];
    const uint32_t sbase = (uint32_t)__cvta_generic_to_shared(sm);

    const int tid = threadIdx.x;
    const int wid = tid >> 5, lid = tid & 31;
    const int wm = wid >> 2, wn = wid & 3;     // warp grid 2(m) x 4(n)
    const int r = lid >> 2, cq = lid & 3;      // fragment lane coords
    const int n0 = blockIdx.x * 128;
    const int m0 = blockIdx.y * 128;
    const float* ga  = g_a + (size_t)m0 * II;
    const float* gb_ = g_b + (size_t)n0 * II;

    float acc[4][4][4];
    #pragma unroll
    for (int i = 0; i < 4; i++)
        #pragma unroll
        for (int j = 0; j < 4; j++)
            #pragma unroll
            for (int q = 0; q < 4; q++) acc[i][j][q] = 0.0f;

    stage_ab(sbase, 0, ga, gb_, 0, tid);

    for (int kb = 0; kb < 32; kb++) {
        if (kb < 31) {
            stage_ab(sbase, (kb + 1) & 1, ga, gb_, kb + 1, tid);
            asm volatile("cp.async.wait_group 1;");
        } else {
            asm volatile("cp.async.wait_group 0;");
        }
        __syncthreads();

        const uint32_t* Au = (const uint32_t*)(sm + (kb & 1) * ATILE);
        const uint32_t* Bu = (const uint32_t*)(sm + (2 + (kb & 1)) * ATILE);

        #pragma unroll
        for (int ks = 0; ks < 4; ks++) {
            const int k0 = ks * 8;
            uint32_t a[4][4], b[4][2];
            #pragma unroll
            for (int i = 0; i < 4; i++) {
                const int base = (wm * 64 + i * 16 + r) * 36 + k0 + cq;
                a[i][0] = Au[base];
                a[i][1] = Au[base + 8 * 36];
                a[i][2] = Au[base + 4];
                a[i][3] = Au[base + 8 * 36 + 4];
            }
            #pragma unroll
            for (int j = 0; j < 4; j++) {
                const int base = (wn * 32 + j * 8 + r) * 36 + k0 + cq;
                b[j][0] = Bu[base];
                b[j][1] = Bu[base + 4];
            }
            #pragma unroll
            for (int i = 0; i < 4; i++)
                #pragma unroll
                for (int j = 0; j < 4; j++)
                    mma_tf32(acc[i][j], a[i], b[j]);
        }
        __syncthreads();
    }

    #pragma unroll
    for (int j = 0; j < 4; j++) {
        const int n = n0 + wn * 32 + j * 8 + cq * 2;
        const float b0 = __ldg(bih + n)     + __ldg(bhh + n);
        const float b1 = __ldg(bih + n + 1) + __ldg(bhh + n + 1);
        #pragma unroll
        for (int i = 0; i < 4; i++) {
            const int m = m0 + wm * 64 + i * 16 + r;
            float2 lo = { acc[i][j][0] + b0, acc[i][j][1] + b1 };
            float2 hi = { acc[i][j][2] + b0, acc[i][j][3] + b1 };
            *(float2*)(C + (size_t)m * G4 + n)       = lo;
            *(float2*)(C + (size_t)(m + 8) * G4 + n) = hi;
        }
    }
}

// ---------------------------------------------------------------------------
// prep: transpose h0 -> g_hT[0] and reset grid barrier.
// ---------------------------------------------------------------------------
__global__ __launch_bounds__(256)
void prep(const float* __restrict__ h0)
{
    const int idx = blockIdx.x * 256 + threadIdx.x;
    const int h = idx >> 6, b = idx & 63;
    g_hT[0][h * 64 + b] = h0[(size_t)b * HH + h];
    if (idx == 0) g_bar = 0;
}

// dummy no-op launches: shift lstm_persist to the 6th launch so
// ncu (-s 5 -c 1) profiles it instead of a phase-1 kernel.
__global__ void noop_pad() { }

// ---------------------------------------------------------------------------
// Persistent recurrence (unchanged from R5 — proven).
// ---------------------------------------------------------------------------
#define WS_OFF 0
#define HB_OFF 32768
#define HB_STG 8192
#define GP_OFF (HB_OFF + 2 * HB_STG)
#define GB_OFF (GP_OFF + 64 * 33)
#define CS_OFF (GB_OFF + 64 * 33)
#define SMEM_FLOATS (CS_OFF + 512)

__global__ __launch_bounds__(256, 1)
void lstm_persist(const float* __restrict__ xg, const float* c0,
                  const float* __restrict__ Whh,
                  float* out, float* hf, float* cf)
{
    extern __shared__ float sm[];
    float* Ws = sm + WS_OFF;
    float* Gp = sm + GP_OFF;
    float* Gb = sm + GB_OFF;
    float* Cs = sm + CS_OFF;
    const uint32_t sbase   = (uint32_t)__cvta_generic_to_shared(sm);
    const uint32_t hb_base = sbase + HB_OFF * 4;

    const int tid = threadIdx.x;
    const int nb  = blockIdx.x;

    {
        const int col   = tid >> 3;
        const int lane8 = tid & 7;
        const int grow  = (col >> 3) * HH + nb * 8 + (col & 7);
        const float* wr = Whh + (size_t)grow * HH;
        for (int kb = 0; kb < II; kb += 32) {
            const int k = kb + lane8 * 4;
            float4 v = *(const float4*)(wr + k);
            Ws[(k + 0) * 32 + col] = v.x;
            Ws[(k + 1) * 32 + col] = v.y;
            Ws[(k + 2) * 32 + col] = v.z;
            Ws[(k + 3) * 32 + col] = v.w;
        }
    }
    #pragma unroll
    for (int r = 0; r < 2; r++) {
        const int e = tid + r * 256;
        const int b = e >> 3, j = e & 7;
        Cs[e] = c0[(size_t)b * HH + nb * 8 + j];
    }
    __syncthreads();

    const int grp = tid >> 7;
    const int t7  = tid & 127;
    const int tx  = t7 & 7;
    const int ty  = t7 >> 3;

    int  src_off[8];
    uint32_t dst_off[8];
    #pragma unroll
    for (int r = 0; r < 8; r++) {
        const int id = tid + r * 256;
        const int g  = id >> 10;
        const int kk = (id >> 4) & 63;
        const int b4 = id & 15;
        src_off[r] = (g * 512 + kk) * 64 + b4 * 4;
        dst_off[r] = (uint32_t)((g * 4096 + kk * 64 + b4 * 4) * 4);
    }

    for (int t = 0; t < TT; t++) {
        const float* hT_cur = g_hT[t & 1];
        float*       hT_nxt = g_hT[(t + 1) & 1];
        const float* xgt    = xg + (size_t)t * BB * G4;
        float*       out_t  = out + (size_t)t * BB * HH;

        float4 xv[4];
        if (grp == 0) {
            const int sect = tx >> 1;
            const int jj0  = (tx & 1) * 4;
            #pragma unroll
            for (int i = 0; i < 4; i++)
                xv[i] = __ldg((const float4*)(xgt + (size_t)(ty * 4 + i) * G4
                              + sect * HH + nb * 8 + jj0));
        }

        #pragma unroll
        for (int r = 0; r < 8; r++)
            cp16(hb_base + dst_off[r], hT_cur + src_off[r]);
        asm volatile("cp.async.commit_group;");

        ull acc[4][2];
        #pragma unroll
        for (int i = 0; i < 4; i++) { acc[i][0] = 0ull; acc[i][1] = 0ull; }

        for (int ch = 0; ch < 8; ch++) {
            if (ch < 7) {
                const uint32_t db = hb_base + ((ch + 1) & 1) * (HB_STG * 4);
                const float* sb = hT_cur + (ch + 1) * 4096;
                #pragma unroll
                for (int r = 0; r < 8; r++)
                    cp16(db + dst_off[r], sb + src_off[r]);
                asm volatile("cp.async.commit_group;");
                asm volatile("cp.async.wait_group 1;");
            } else {
                asm volatile("cp.async.wait_group 0;");
            }
            __syncthreads();

            const float* hsg = sm + HB_OFF + (ch & 1) * HB_STG + grp * 4096;
            const int kbase = grp * 512 + ch * 64;
            #pragma unroll 4
            for (int kk = 0; kk < 64; kk++) {
                const float4 hv = *(const float4*)&hsg[kk * 64 + ty * 4];
                const ulonglong2 wv = *(const ulonglong2*)&Ws[(kbase + kk) * 32 + tx * 4];
                const ull a0 = pack2(hv.x), a1 = pack2(hv.y);
                const ull a2 = pack2(hv.z), a3 = pack2(hv.w);
                fma2(acc[0][0], a0, wv.x); fma2(acc[0][1], a0, wv.y);
                fma2(acc[1][0], a1, wv.x); fma2(acc[1][1], a1, wv.y);
                fma2(acc[2][0], a2, wv.x); fma2(acc[2][1], a2, wv.y);
                fma2(acc[3][0], a3, wv.x); fma2(acc[3][1], a3, wv.y);
            }
            __syncthreads();
        }

        if (grp == 1) {
            #pragma unroll
            for (int i = 0; i < 4; i++) {
                const int b = ty * 4 + i;
                float2 p0 = unpack2(acc[i][0]);
                float2 p1 = unpack2(acc[i][1]);
                Gp[b * 33 + tx * 4 + 0] = p0.x;
                Gp[b * 33 + tx * 4 + 1] = p0.y;
                Gp[b * 33 + tx * 4 + 2] = p1.x;
                Gp[b * 33 + tx * 4 + 3] = p1.y;
            }
        }
        __syncthreads();
        if (grp == 0) {
            #pragma unroll
            for (int i = 0; i < 4; i++) {
                const int b = ty * 4 + i;
                float2 p0 = unpack2(acc[i][0]);
                float2 p1 = unpack2(acc[i][1]);
                Gb[b * 33 + tx * 4 + 0] = p0.x + Gp[b * 33 + tx * 4 + 0] + xv[i].x;
                Gb[b * 33 + tx * 4 + 1] = p0.y + Gp[b * 33 + tx * 4 + 1] + xv[i].y;
                Gb[b * 33 + tx * 4 + 2] = p1.x + Gp[b * 33 + tx * 4 + 2] + xv[i].z;
                Gb[b * 33 + tx * 4 + 3] = p1.y + Gp[b * 33 + tx * 4 + 3] + xv[i].w;
            }
        }
        __syncthreads();

        #pragma unroll
        for (int r = 0; r < 2; r++) {
            const int e = tid + r * 256;
            const int b = e >> 3, j = e & 7;
            const float ig = Gb[b * 33 + j];
            const float fg = Gb[b * 33 + 8 + j];
            const float gg = Gb[b * 33 + 16 + j];
            const float og = Gb[b * 33 + 24 + j];
            const float si = 1.0f / (1.0f + expf(-ig));
            const float sf = 1.0f / (1.0f + expf(-fg));
            const float so = 1.0f / (1.0f + expf(-og));
            const float tg = tanhf(gg);
            const float cn = sf * Cs[e] + si * tg;
            const float hn = so * tanhf(cn);
            Cs[e] = cn;
            const int hc = nb * 8 + j;
            __stcg(out_t + (size_t)b * HH + hc, hn);
            __stcg(hT_nxt + hc * 64 + b, hn);
            if (t == TT - 1) {
                hf[(size_t)b * HH + hc] = hn;
                cf[(size_t)b * HH + hc] = cn;
            }
        }

        __syncthreads();
        if (tid == 0) {
            __threadfence();
            const unsigned target = (unsigned)(t + 1) * GRID;
            atomicAdd(&g_bar, 1u);
            while (*(volatile unsigned*)&g_bar < target) { }
            __threadfence();
        }
        __syncthreads();
    }
}

// ---------------------------------------------------------------------------
extern "C" void kernel_launch(void* const* d_in, const int* in_sizes, int n_in,
                              void* d_out, int out_size)
{
    const float* input = (const float*)d_in[0];
    const float* h0    = (const float*)d_in[1];
    const float* c0    = (const float*)d_in[2];
    const float* w_ih  = (const float*)d_in[3];
    const float* w_hh  = (const float*)d_in[4];
    const float* b_ih  = (const float*)d_in[5];
    const float* b_hh  = (const float*)d_in[6];

    float* outputs = (float*)d_out;                 // [T, B, H]
    float* hf = outputs + (size_t)TT * BB * HH;
    float* cf = hf + (size_t)BB * HH;

    float* xg = nullptr;
    cudaGetSymbolAddress((void**)&xg, g_xg);

    cudaFuncSetAttribute(gemm_mma,
                         cudaFuncAttributeMaxDynamicSharedMemorySize,
                         GEMM_SMEM);
    cudaFuncSetAttribute(lstm_persist,
                         cudaFuncAttributeMaxDynamicSharedMemorySize,
                         (int)(SMEM_FLOATS * sizeof(float)));

    cvt_tf32<<<T_F4 / 256, 256>>>(input, w_ih);
    gemm_mma<<<dim3(32, 256), 256, GEMM_SMEM>>>(b_ih, b_hh, xg);
    prep<<<256, 256>>>(h0);
    noop_pad<<<1, 32>>>();
    noop_pad<<<1, 32>>>();
    lstm_persist<<<GRID, 256, SMEM_FLOATS * sizeof(float)>>>(xg, c0, w_hh,
                                                             outputs, hf, cf);
}

// round 11
// speedup vs baseline: 3.2647x; 1.5630x over previous
#include <cuda_runtime.h>
#include <math.h>
#include <stdint.h>

#define TT   512
#define BB   64
#define II   1024
#define HH   1024
#define G4   4096      // 4*H
#define GRID 128       // persistent CTAs for recurrence

typedef unsigned long long ull;

// Static device scratch (no runtime alloc)
__device__ float g_xg[(size_t)TT * BB * G4];     // x_gates [T, B, 4H]
__device__ float g_a[(size_t)TT * BB * II];      // tf32-rounded input  [32768, 1024]
__device__ float g_b[(size_t)G4 * II];           // tf32-rounded w_ih   [4096, 1024]
__device__ float g_hr[2][BB * HH];               // rna-rounded h ping-pong [b][h]
__device__ unsigned g_bar;

__device__ __forceinline__ void cp16(uint32_t dst_smem, const void* src) {
    asm volatile("cp.async.cg.shared.global [%0], [%1], 16;"
                 :: "r"(dst_smem), "l"(src));
}
__device__ __forceinline__ uint32_t rna_tf32(float x) {
    uint32_t r; asm("cvt.rna.tf32.f32 %0, %1;" : "=r"(r) : "f"(x)); return r;
}
__device__ __forceinline__ void mma_tf32(float* c, const uint32_t* a,
                                         const uint32_t* b) {
    asm("mma.sync.aligned.m16n8k8.row.col.f32.tf32.tf32.f32 "
        "{%0,%1,%2,%3}, {%4,%5,%6,%7}, {%8,%9}, {%0,%1,%2,%3};"
        : "+f"(c[0]), "+f"(c[1]), "+f"(c[2]), "+f"(c[3])
        : "r"(a[0]), "r"(a[1]), "r"(a[2]), "r"(a[3]), "r"(b[0]), "r"(b[1]));
}

// ---------------------------------------------------------------------------
// cvt pass: round input + w_ih to tf32 (rna) into g_a / g_b.
// ---------------------------------------------------------------------------
#define A_F4 8388608   // input float4 count
#define T_F4 9437184   // total float4 count
__global__ __launch_bounds__(256)
void cvt_tf32(const float* __restrict__ in, const float* __restrict__ wih)
{
    const int idx = blockIdx.x * 256 + threadIdx.x;
    const float4* src; float* dst; int i4;
    if (idx < A_F4) { src = (const float4*)in;  dst = g_a; i4 = idx; }
    else            { src = (const float4*)wih; dst = g_b; i4 = idx - A_F4; }
    float4 v = src[i4];
    uint4 o;
    o.x = rna_tf32(v.x); o.y = rna_tf32(v.y);
    o.z = rna_tf32(v.z); o.w = rna_tf32(v.w);
    *(uint4*)(dst + (size_t)i4 * 4) = o;
}

// ---------------------------------------------------------------------------
// Phase 1: tf32 mma.sync GEMM (proven in R10).
// ---------------------------------------------------------------------------
#define ATILE 4608
#define GEMM_SMEM (4 * ATILE * 4)

__device__ __forceinline__ void stage_ab(uint32_t sb, int s, const float* ga,
                                         const float* gb_, int kb, int tid)
{
    const uint32_t ab = sb + (uint32_t)(s * ATILE) * 4;
    const uint32_t bbse = sb + (uint32_t)((2 + s) * ATILE) * 4;
    #pragma unroll
    for (int r = 0; r < 4; r++) {
        const int id = tid + r * 256;
        const int row = id >> 3, k = (id & 7) * 4;
        cp16(ab + (uint32_t)(row * 36 + k) * 4,
             ga + (size_t)row * II + kb * 32 + k);
    }
    #pragma unroll
    for (int r = 0; r < 4; r++) {
        const int id = tid + r * 256;
        const int row = id >> 3, k = (id & 7) * 4;
        cp16(bbse + (uint32_t)(row * 36 + k) * 4,
             gb_ + (size_t)row * II + kb * 32 + k);
    }
    asm volatile("cp.async.commit_group;");
}

__global__ __launch_bounds__(256, 2)
void gemm_mma(const float* __restrict__ bih, const float* __restrict__ bhh,
              float* __restrict__ C)
{
    extern __shared__ float sm[];
    const uint32_t sbase = (uint32_t)__cvta_generic_to_shared(sm);

    const int tid = threadIdx.x;
    const int wid = tid >> 5, lid = tid & 31;
    const int wm = wid >> 2, wn = wid & 3;
    const int r = lid >> 2, cq = lid & 3;
    const int n0 = blockIdx.x * 128;
    const int m0 = blockIdx.y * 128;
    const float* ga  = g_a + (size_t)m0 * II;
    const float* gb_ = g_b + (size_t)n0 * II;

    float acc[4][4][4];
    #pragma unroll
    for (int i = 0; i < 4; i++)
        #pragma unroll
        for (int j = 0; j < 4; j++)
            #pragma unroll
            for (int q = 0; q < 4; q++) acc[i][j][q] = 0.0f;

    stage_ab(sbase, 0, ga, gb_, 0, tid);

    for (int kb = 0; kb < 32; kb++) {
        if (kb < 31) {
            stage_ab(sbase, (kb + 1) & 1, ga, gb_, kb + 1, tid);
            asm volatile("cp.async.wait_group 1;");
        } else {
            asm volatile("cp.async.wait_group 0;");
        }
        __syncthreads();

        const uint32_t* Au = (const uint32_t*)(sm + (kb & 1) * ATILE);
        const uint32_t* Bu = (const uint32_t*)(sm + (2 + (kb & 1)) * ATILE);

        #pragma unroll
        for (int ks = 0; ks < 4; ks++) {
            const int k0 = ks * 8;
            uint32_t a[4][4], b[4][2];
            #pragma unroll
            for (int i = 0; i < 4; i++) {
                const int base = (wm * 64 + i * 16 + r) * 36 + k0 + cq;
                a[i][0] = Au[base];
                a[i][1] = Au[base + 8 * 36];
                a[i][2] = Au[base + 4];
                a[i][3] = Au[base + 8 * 36 + 4];
            }
            #pragma unroll
            for (int j = 0; j < 4; j++) {
                const int base = (wn * 32 + j * 8 + r) * 36 + k0 + cq;
                b[j][0] = Bu[base];
                b[j][1] = Bu[base + 4];
            }
            #pragma unroll
            for (int i = 0; i < 4; i++)
                #pragma unroll
                for (int j = 0; j < 4; j++)
                    mma_tf32(acc[i][j], a[i], b[j]);
        }
        __syncthreads();
    }

    #pragma unroll
    for (int j = 0; j < 4; j++) {
        const int n = n0 + wn * 32 + j * 8 + cq * 2;
        const float b0 = __ldg(bih + n)     + __ldg(bhh + n);
        const float b1 = __ldg(bih + n + 1) + __ldg(bhh + n + 1);
        #pragma unroll
        for (int i = 0; i < 4; i++) {
            const int m = m0 + wm * 64 + i * 16 + r;
            float2 lo = { acc[i][j][0] + b0, acc[i][j][1] + b1 };
            float2 hi = { acc[i][j][2] + b0, acc[i][j][3] + b1 };
            *(float2*)(C + (size_t)m * G4 + n)       = lo;
            *(float2*)(C + (size_t)(m + 8) * G4 + n) = hi;
        }
    }
}

// ---------------------------------------------------------------------------
// prep: rna-round h0 -> g_hr[0] ([b][h], same layout) and reset grid barrier.
// ---------------------------------------------------------------------------
__global__ __launch_bounds__(256)
void prep(const float* __restrict__ h0)
{
    const int i4 = blockIdx.x * 256 + threadIdx.x;   // 0..16383
    float4 v = ((const float4*)h0)[i4];
    uint4 o;
    o.x = rna_tf32(v.x); o.y = rna_tf32(v.y);
    o.z = rna_tf32(v.z); o.w = rna_tf32(v.w);
    *(uint4*)(g_hr[0] + (size_t)i4 * 4) = o;
    if (i4 == 0) g_bar = 0;
}

// ---------------------------------------------------------------------------
// Persistent recurrence, tensorized. 128 CTAs x 256 threads (8 warps).
// CTA nb owns h-cols [nb*8,nb*8+8) -> 32 gate rows (local col = sect*8+j).
// gates[64,32] = h[64,1024] @ Wslice[32,1024]^T via mma.sync tf32.
// Warp w: m-tile rows (w>>1)*16..+15, n-tiles (w&1)*16 + {0,8}; full-K
// register accumulation (no cross-warp reduction).
// W slice rna-rounded in SMEM (row stride 1028 -> conflict-free frags);
// h staged per 128-k chunk via double-buffered cp.async from g_hr (row
// stride 132 -> conflict-free). Pointwise fused; h written twice: exact
// fp32 to out, rna-rounded to g_hr for next step's MMA.
//
// SMEM floats: Ws 32x1028 = 32896 | Hs 2 x 64x132 = 16896 |
//              Gb 64x34 = 2176 | Cs 512  -> total 52480 (209920 B)
// ---------------------------------------------------------------------------
#define WS_STRIDE 1028
#define HS_OFF 32896
#define HS_STG (64 * 132)
#define GB_OFF (HS_OFF + 2 * HS_STG)
#define CS_OFF (GB_OFF + 64 * 34)
#define SMEM_FLOATS (CS_OFF + 512)

__global__ __launch_bounds__(256, 1)
void lstm_persist(const float* __restrict__ xg, const float* c0,
                  const float* __restrict__ Whh,
                  float* out, float* hf, float* cf)
{
    extern __shared__ float sm[];
    float* Ws = sm;
    float* Gb = sm + GB_OFF;
    float* Cs = sm + CS_OFF;
    const uint32_t sbase = (uint32_t)__cvta_generic_to_shared(sm);
    const uint32_t hsb   = sbase + HS_OFF * 4;

    const int tid = threadIdx.x;
    const int nb  = blockIdx.x;            // 0..127

    // ---- load W slice (32 gate rows x 1024), rna-rounded -> Ws[col][k] ----
    {
        const int col = tid >> 3;          // 0..31 local gate col
        const int l8  = tid & 7;
        const int grow = (col >> 3) * HH + nb * 8 + (col & 7);
        const float* wr = Whh + (size_t)grow * HH;
        for (int k0 = l8 * 4; k0 < II; k0 += 32) {
            float4 v = *(const float4*)(wr + k0);
            uint4 o;
            o.x = rna_tf32(v.x); o.y = rna_tf32(v.y);
            o.z = rna_tf32(v.z); o.w = rna_tf32(v.w);
            *(uint4*)(Ws + col * WS_STRIDE + k0) = o;
        }
    }
    #pragma unroll
    for (int r8 = 0; r8 < 2; r8++) {
        const int e = tid + r8 * 256;
        const int b = e >> 3, j = e & 7;
        Cs[e] = c0[(size_t)b * HH + nb * 8 + j];
    }
    __syncthreads();

    const int wid = tid >> 5, lid = tid & 31;
    const int r  = lid >> 2, cq = lid & 3;
    const int wm0 = (wid >> 1) * 16;       // batch-tile base
    const int wn0 = (wid & 1) * 16;        // col-tile base (+0 / +8)

    for (int t = 0; t < TT; t++) {
        const float* hr_cur = g_hr[t & 1];
        float*       hr_nxt = g_hr[(t + 1) & 1];
        const float* xgt    = xg + (size_t)t * BB * G4;
        float*       out_t  = out + (size_t)t * BB * HH;

        // ---- prefetch this thread's xg gate values (used in pointwise) ----
        float xvv[2][4];
        #pragma unroll
        for (int r8 = 0; r8 < 2; r8++) {
            const int e = tid + r8 * 256;
            const int b = e >> 3, j = e & 7;
            #pragma unroll
            for (int s = 0; s < 4; s++)
                xvv[r8][s] = __ldg(xgt + (size_t)b * G4 + s * HH + nb * 8 + j);
        }

        // ---- prologue: stage k-chunk 0 ----
        #pragma unroll
        for (int r8 = 0; r8 < 8; r8++) {
            const int id = tid + r8 * 256;     // 2048 float4s
            const int b = id >> 5, q = id & 31;
            cp16(hsb + (uint32_t)(b * 132 + q * 4) * 4,
                 hr_cur + (size_t)b * HH + q * 4);
        }
        asm volatile("cp.async.commit_group;");

        float acc[2][4];
        #pragma unroll
        for (int s = 0; s < 2; s++)
            #pragma unroll
            for (int q = 0; q < 4; q++) acc[s][q] = 0.0f;

        for (int ch = 0; ch < 8; ch++) {
            if (ch < 7) {
                const uint32_t db = hsb + (uint32_t)(((ch + 1) & 1) * HS_STG) * 4;
                const float* sb = hr_cur + (ch + 1) * 128;
                #pragma unroll
                for (int r8 = 0; r8 < 8; r8++) {
                    const int id = tid + r8 * 256;
                    const int b = id >> 5, q = id & 31;
                    cp16(db + (uint32_t)(b * 132 + q * 4) * 4,
                         sb + (size_t)b * HH + q * 4);
                }
                asm volatile("cp.async.commit_group;");
                asm volatile("cp.async.wait_group 1;");
            } else {
                asm volatile("cp.async.wait_group 0;");
            }
            __syncthreads();

            const uint32_t* Hu = (const uint32_t*)(sm + HS_OFF + (ch & 1) * HS_STG);
            const uint32_t* Wu = (const uint32_t*)Ws;
            const int kb = ch * 128;

            #pragma unroll
            for (int ks = 0; ks < 16; ks++) {
                const int k = ks * 8;
                uint32_t a[4], b0[2], b1[2];
                const int abase = (wm0 + r) * 132 + k + cq;
                a[0] = Hu[abase];
                a[1] = Hu[abase + 8 * 132];
                a[2] = Hu[abase + 4];
                a[3] = Hu[abase + 8 * 132 + 4];
                const int bbase = (wn0 + r) * WS_STRIDE + kb + k + cq;
                b0[0] = Wu[bbase];
                b0[1] = Wu[bbase + 4];
                b1[0] = Wu[bbase + 8 * WS_STRIDE];
                b1[1] = Wu[bbase + 8 * WS_STRIDE + 4];
                mma_tf32(acc[0], a, b0);
                mma_tf32(acc[1], a, b1);
            }
            __syncthreads();
        }

        // ---- write gate partials to Gb[b][col] ----
        #pragma unroll
        for (int s = 0; s < 2; s++) {
            const int n = wn0 + s * 8 + cq * 2;
            *(float2*)&Gb[(wm0 + r) * 34 + n]     = make_float2(acc[s][0], acc[s][1]);
            *(float2*)&Gb[(wm0 + r + 8) * 34 + n] = make_float2(acc[s][2], acc[s][3]);
        }
        __syncthreads();

        // ---- fused pointwise LSTM update ----
        #pragma unroll
        for (int r8 = 0; r8 < 2; r8++) {
            const int e = tid + r8 * 256;
            const int b = e >> 3, j = e & 7;
            const float ig = Gb[b * 34 + j]      + xvv[r8][0];
            const float fg = Gb[b * 34 + 8 + j]  + xvv[r8][1];
            const float gg = Gb[b * 34 + 16 + j] + xvv[r8][2];
            const float og = Gb[b * 34 + 24 + j] + xvv[r8][3];
            const float si = 1.0f / (1.0f + expf(-ig));
            const float sf = 1.0f / (1.0f + expf(-fg));
            const float so = 1.0f / (1.0f + expf(-og));
            const float tg = tanhf(gg);
            const float cn = sf * Cs[e] + si * tg;
            const float hn = so * tanhf(cn);
            Cs[e] = cn;
            const int hc = nb * 8 + j;
            __stcg(out_t + (size_t)b * HH + hc, hn);
            __stcg(hr_nxt + (size_t)b * HH + hc, __uint_as_float(rna_tf32(hn)));
            if (t == TT - 1) {
                hf[(size_t)b * HH + hc] = hn;
                cf[(size_t)b * HH + hc] = cn;
            }
        }

        // ---- grid-wide barrier ----
        __syncthreads();
        if (tid == 0) {
            __threadfence();
            const unsigned target = (unsigned)(t + 1) * GRID;
            atomicAdd(&g_bar, 1u);
            while (*(volatile unsigned*)&g_bar < target) { }
            __threadfence();
        }
        __syncthreads();
    }
}

// ---------------------------------------------------------------------------
extern "C" void kernel_launch(void* const* d_in, const int* in_sizes, int n_in,
                              void* d_out, int out_size)
{
    const float* input = (const float*)d_in[0];
    const float* h0    = (const float*)d_in[1];
    const float* c0    = (const float*)d_in[2];
    const float* w_ih  = (const float*)d_in[3];
    const float* w_hh  = (const float*)d_in[4];
    const float* b_ih  = (const float*)d_in[5];
    const float* b_hh  = (const float*)d_in[6];

    float* outputs = (float*)d_out;                 // [T, B, H]
    float* hf = outputs + (size_t)TT * BB * HH;
    float* cf = hf + (size_t)BB * HH;

    float* xg = nullptr;
    cudaGetSymbolAddress((void**)&xg, g_xg);

    cudaFuncSetAttribute(gemm_mma,
                         cudaFuncAttributeMaxDynamicSharedMemorySize,
                         GEMM_SMEM);
    cudaFuncSetAttribute(lstm_persist,
                         cudaFuncAttributeMaxDynamicSharedMemorySize,
                         (int)(SMEM_FLOATS * sizeof(float)));

    cvt_tf32<<<T_F4 / 256, 256>>>(input, w_ih);
    gemm_mma<<<dim3(32, 256), 256, GEMM_SMEM>>>(b_ih, b_hh, xg);
    prep<<<64, 256>>>(h0);
    lstm_persist<<<GRID, 256, SMEM_FLOATS * sizeof(float)>>>(xg, c0, w_hh,
                                                             outputs, hf, cf);
}

// round 14
// speedup vs baseline: 3.3253x; 1.0186x over previous
#include <cuda_runtime.h>
#include <math.h>
#include <stdint.h>

#define TT   512
#define BB   64
#define II   1024
#define HH   1024
#define G4   4096      // 4*H
#define GRID 128       // persistent CTAs for recurrence

typedef unsigned long long ull;

// Static device scratch (no runtime alloc)
__device__ float g_xg[(size_t)TT * BB * G4];     // x_gates [T, B, 4H]
__device__ float g_a[(size_t)TT * BB * II];      // tf32-rounded input  [32768, 1024]
__device__ float g_b[(size_t)G4 * II];           // tf32-rounded w_ih   [4096, 1024]
__device__ float g_hr[2][BB * HH];               // rna-rounded h ping-pong [b][h]
__device__ unsigned g_bar;

__device__ __forceinline__ void cp16(uint32_t dst_smem, const void* src) {
    asm volatile("cp.async.cg.shared.global [%0], [%1], 16;"
                 :: "r"(dst_smem), "l"(src));
}
__device__ __forceinline__ uint32_t rna_tf32(float x) {
    uint32_t r; asm("cvt.rna.tf32.f32 %0, %1;" : "=r"(r) : "f"(x)); return r;
}
__device__ __forceinline__ void mma_tf32(float* c, const uint32_t* a,
                                         const uint32_t* b) {
    asm("mma.sync.aligned.m16n8k8.row.col.f32.tf32.tf32.f32 "
        "{%0,%1,%2,%3}, {%4,%5,%6,%7}, {%8,%9}, {%0,%1,%2,%3};"
        : "+f"(c[0]), "+f"(c[1]), "+f"(c[2]), "+f"(c[3])
        : "r"(a[0]), "r"(a[1]), "r"(a[2]), "r"(a[3]), "r"(b[0]), "r"(b[1]));
}

// ---------------------------------------------------------------------------
// cvt pass: round input + w_ih to tf32 (rna) into g_a / g_b.
// ---------------------------------------------------------------------------
#define A_F4 8388608   // input float4 count
#define T_F4 9437184   // total float4 count
__global__ __launch_bounds__(256)
void cvt_tf32(const float* __restrict__ in, const float* __restrict__ wih)
{
    const int idx = blockIdx.x * 256 + threadIdx.x;
    const float4* src; float* dst; int i4;
    if (idx < A_F4) { src = (const float4*)in;  dst = g_a; i4 = idx; }
    else            { src = (const float4*)wih; dst = g_b; i4 = idx - A_F4; }
    float4 v = src[i4];
    uint4 o;
    o.x = rna_tf32(v.x); o.y = rna_tf32(v.y);
    o.z = rna_tf32(v.z); o.w = rna_tf32(v.w);
    *(uint4*)(dst + (size_t)i4 * 4) = o;
}

// ---------------------------------------------------------------------------
// Phase 1: tf32 mma.sync GEMM (proven in R10/R11).
// ---------------------------------------------------------------------------
#define ATILE 4608
#define GEMM_SMEM (4 * ATILE * 4)

__device__ __forceinline__ void stage_ab(uint32_t sb, int s, const float* ga,
                                         const float* gb_, int kb, int tid)
{
    const uint32_t ab = sb + (uint32_t)(s * ATILE) * 4;
    const uint32_t bbse = sb + (uint32_t)((2 + s) * ATILE) * 4;
    #pragma unroll
    for (int r = 0; r < 4; r++) {
        const int id = tid + r * 256;
        const int row = id >> 3, k = (id & 7) * 4;
        cp16(ab + (uint32_t)(row * 36 + k) * 4,
             ga + (size_t)row * II + kb * 32 + k);
    }
    #pragma unroll
    for (int r = 0; r < 4; r++) {
        const int id = tid + r * 256;
        const int row = id >> 3, k = (id & 7) * 4;
        cp16(bbse + (uint32_t)(row * 36 + k) * 4,
             gb_ + (size_t)row * II + kb * 32 + k);
    }
    asm volatile("cp.async.commit_group;");
}

__global__ __launch_bounds__(256, 2)
void gemm_mma(const float* __restrict__ bih, const float* __restrict__ bhh,
              float* __restrict__ C)
{
    extern __shared__ float sm[];
    const uint32_t sbase = (uint32_t)__cvta_generic_to_shared(sm);

    const int tid = threadIdx.x;
    const int wid = tid >> 5, lid = tid & 31;
    const int wm = wid >> 2, wn = wid & 3;
    const int r = lid >> 2, cq = lid & 3;
    const int n0 = blockIdx.x * 128;
    const int m0 = blockIdx.y * 128;
    const float* ga  = g_a + (size_t)m0 * II;
    const float* gb_ = g_b + (size_t)n0 * II;

    float acc[4][4][4];
    #pragma unroll
    for (int i = 0; i < 4; i++)
        #pragma unroll
        for (int j = 0; j < 4; j++)
            #pragma unroll
            for (int q = 0; q < 4; q++) acc[i][j][q] = 0.0f;

    stage_ab(sbase, 0, ga, gb_, 0, tid);

    for (int kb = 0; kb < 32; kb++) {
        if (kb < 31) {
            stage_ab(sbase, (kb + 1) & 1, ga, gb_, kb + 1, tid);
            asm volatile("cp.async.wait_group 1;");
        } else {
            asm volatile("cp.async.wait_group 0;");
        }
        __syncthreads();

        const uint32_t* Au = (const uint32_t*)(sm + (kb & 1) * ATILE);
        const uint32_t* Bu = (const uint32_t*)(sm + (2 + (kb & 1)) * ATILE);

        #pragma unroll
        for (int ks = 0; ks < 4; ks++) {
            const int k0 = ks * 8;
            uint32_t a[4][4], b[4][2];
            #pragma unroll
            for (int i = 0; i < 4; i++) {
                const int base = (wm * 64 + i * 16 + r) * 36 + k0 + cq;
                a[i][0] = Au[base];
                a[i][1] = Au[base + 8 * 36];
                a[i][2] = Au[base + 4];
                a[i][3] = Au[base + 8 * 36 + 4];
            }
            #pragma unroll
            for (int j = 0; j < 4; j++) {
                const int base = (wn * 32 + j * 8 + r) * 36 + k0 + cq;
                b[j][0] = Bu[base];
                b[j][1] = Bu[base + 4];
            }
            #pragma unroll
            for (int i = 0; i < 4; i++)
                #pragma unroll
                for (int j = 0; j < 4; j++)
                    mma_tf32(acc[i][j], a[i], b[j]);
        }
        __syncthreads();
    }

    #pragma unroll
    for (int j = 0; j < 4; j++) {
        const int n = n0 + wn * 32 + j * 8 + cq * 2;
        const float b0 = __ldg(bih + n)     + __ldg(bhh + n);
        const float b1 = __ldg(bih + n + 1) + __ldg(bhh + n + 1);
        #pragma unroll
        for (int i = 0; i < 4; i++) {
            const int m = m0 + wm * 64 + i * 16 + r;
            float2 lo = { acc[i][j][0] + b0, acc[i][j][1] + b1 };
            float2 hi = { acc[i][j][2] + b0, acc[i][j][3] + b1 };
            *(float2*)(C + (size_t)m * G4 + n)       = lo;
            *(float2*)(C + (size_t)(m + 8) * G4 + n) = hi;
        }
    }
}

// ---------------------------------------------------------------------------
// prep: rna-round h0 -> g_hr[0] and reset grid barrier.
// ---------------------------------------------------------------------------
__global__ __launch_bounds__(256)
void prep(const float* __restrict__ h0)
{
    const int i4 = blockIdx.x * 256 + threadIdx.x;   // 0..16383
    float4 v = ((const float4*)h0)[i4];
    uint4 o;
    o.x = rna_tf32(v.x); o.y = rna_tf32(v.y);
    o.z = rna_tf32(v.z); o.w = rna_tf32(v.w);
    *(uint4*)(g_hr[0] + (size_t)i4 * 4) = o;
    if (i4 == 0) g_bar = 0;
}

// ---------------------------------------------------------------------------
// Persistent recurrence, tensorized + split-K-across-warps.
// 128 CTAs x 256 threads (8 warps). CTA nb owns h-cols [nb*8,nb*8+8)
// -> 32 gate rows. Warp w owns k-slice [w*16, w*16+16) of each 128-k chunk
// and computes the FULL 64x32 gate tile (acc[4mt][4nt][4]); one 8-way
// smem reduction per step (staging buffers reused as scratch).
// One __syncthreads per chunk: [wait_group 0; sync; issue cp(ch+1); mma(ch)].
//
// SMEM floats: Ws 32x1028 = 32896 | Hs 2 x 64x132 = 16896 (also Gpart 8x2112)
//              Gb 64x34 = 2176 | Cs 512  -> 52480 floats (209920 B)
// ---------------------------------------------------------------------------
#define WS_STRIDE 1028
#define HS_OFF 32896
#define HS_STG (64 * 132)
#define GB_OFF (HS_OFF + 2 * HS_STG)
#define CS_OFF (GB_OFF + 64 * 34)
#define SMEM_FLOATS (CS_OFF + 512)

__global__ __launch_bounds__(256, 1)
void lstm_persist(const float* __restrict__ xg, const float* c0,
                  const float* __restrict__ Whh,
                  float* out, float* hf, float* cf)
{
    extern __shared__ float sm[];
    float* Ws = sm;
    float* Gpart = sm + HS_OFF;            // aliases Hs after K-loop
    float* Gb = sm + GB_OFF;
    float* Cs = sm + CS_OFF;
    const uint32_t sbase = (uint32_t)__cvta_generic_to_shared(sm);
    const uint32_t hsb   = sbase + HS_OFF * 4;

    const int tid = threadIdx.x;
    const int nb  = blockIdx.x;            // 0..127

    // ---- load W slice (32 gate rows x 1024), rna-rounded -> Ws[col][k] ----
    {
        const int col = tid >> 3;          // 0..31 local gate col
        const int l8  = tid & 7;
        const int grow = (col >> 3) * HH + nb * 8 + (col & 7);
        const float* wr = Whh + (size_t)grow * HH;
        for (int k0 = l8 * 4; k0 < II; k0 += 32) {
            float4 v = *(const float4*)(wr + k0);
            uint4 o;
            o.x = rna_tf32(v.x); o.y = rna_tf32(v.y);
            o.z = rna_tf32(v.z); o.w = rna_tf32(v.w);
            *(uint4*)(Ws + col * WS_STRIDE + k0) = o;
        }
    }
    #pragma unroll
    for (int r8 = 0; r8 < 2; r8++) {
        const int e = tid + r8 * 256;
        const int b = e >> 3, j = e & 7;
        Cs[e] = c0[(size_t)b * HH + nb * 8 + j];
    }
    __syncthreads();

    const int wid = tid >> 5, lid = tid & 31;
    const int r  = lid >> 2, cq = lid & 3;
    const int kw = wid * 16;               // warp's k-offset within chunk

    for (int t = 0; t < TT; t++) {
        const float* hr_cur = g_hr[t & 1];
        float*       hr_nxt = g_hr[(t + 1) & 1];
        const float* xgt    = xg + (size_t)t * BB * G4;
        float*       out_t  = out + (size_t)t * BB * HH;

        // ---- prefetch this thread's xg gate values (pointwise) ----
        float xvv[2][4];
        #pragma unroll
        for (int r8 = 0; r8 < 2; r8++) {
            const int e = tid + r8 * 256;
            const int b = e >> 3, j = e & 7;
            #pragma unroll
            for (int s = 0; s < 4; s++)
                xvv[r8][s] = __ldg(xgt + (size_t)b * G4 + s * HH + nb * 8 + j);
        }

        // ---- prologue: stage k-chunk 0 ----
        #pragma unroll
        for (int r8 = 0; r8 < 8; r8++) {
            const int id = tid + r8 * 256;
            const int b = id >> 5, q = id & 31;
            cp16(hsb + (uint32_t)(b * 132 + q * 4) * 4,
                 hr_cur + (size_t)b * HH + q * 4);
        }
        asm volatile("cp.async.commit_group;");

        float acc[4][4][4];
        #pragma unroll
        for (int i = 0; i < 4; i++)
            #pragma unroll
            for (int j = 0; j < 4; j++)
                #pragma unroll
                for (int q = 0; q < 4; q++) acc[i][j][q] = 0.0f;

        for (int ch = 0; ch < 8; ch++) {
            asm volatile("cp.async.wait_group 0;");
            __syncthreads();               // data visible; prev buffer free

            if (ch < 7) {                  // issue next chunk (overlaps mma)
                const uint32_t db = hsb + (uint32_t)(((ch + 1) & 1) * HS_STG) * 4;
                const float* sb = hr_cur + (ch + 1) * 128;
                #pragma unroll
                for (int r8 = 0; r8 < 8; r8++) {
                    const int id = tid + r8 * 256;
                    const int b = id >> 5, q = id & 31;
                    cp16(db + (uint32_t)(b * 132 + q * 4) * 4,
                         sb + (size_t)b * HH + q * 4);
                }
                asm volatile("cp.async.commit_group;");
            }

            const uint32_t* Hu = (const uint32_t*)(sm + HS_OFF + (ch & 1) * HS_STG);
            const uint32_t* Wu = (const uint32_t*)Ws;
            const int kglob = ch * 128 + kw;

            #pragma unroll
            for (int kt2 = 0; kt2 < 2; kt2++) {
                const int kl = kw + kt2 * 8;       // within chunk
                const int kg = kglob + kt2 * 8;    // global k
                uint32_t b_[4][2];
                #pragma unroll
                for (int nt = 0; nt < 4; nt++) {
                    const int bbase = (nt * 8 + r) * WS_STRIDE + kg + cq;
                    b_[nt][0] = Wu[bbase];
                    b_[nt][1] = Wu[bbase + 4];
                }
                #pragma unroll
                for (int mt = 0; mt < 4; mt++) {
                    uint32_t a[4];
                    const int abase = (mt * 16 + r) * 132 + kl + cq;
                    a[0] = Hu[abase];
                    a[1] = Hu[abase + 8 * 132];
                    a[2] = Hu[abase + 4];
                    a[3] = Hu[abase + 8 * 132 + 4];
                    #pragma unroll
                    for (int nt = 0; nt < 4; nt++)
                        mma_tf32(acc[mt][nt], a, b_[nt]);
                }
            }
            __syncthreads();               // all warps done before buffer reuse
        }

        // ---- write per-warp partials to Gpart[w] (aliases Hs) ----
        {
            float* gp = Gpart + wid * 2112;
            #pragma unroll
            for (int mt = 0; mt < 4; mt++)
                #pragma unroll
                for (int nt = 0; nt < 4; nt++) {
                    const int row = mt * 16 + r;
                    const int col = nt * 8 + cq * 2;
                    gp[row * 33 + col]           = acc[mt][nt][0];
                    gp[row * 33 + col + 1]       = acc[mt][nt][1];
                    gp[(row + 8) * 33 + col]     = acc[mt][nt][2];
                    gp[(row + 8) * 33 + col + 1] = acc[mt][nt][3];
                }
        }
        __syncthreads();

        // ---- 8-way reduction -> Gb[b][col] ----
        {
            const int b = tid >> 2;
            const int colb = (tid & 3) * 8;
            #pragma unroll
            for (int j = 0; j < 8; j++) {
                const int off = b * 33 + colb + j;
                float s = Gpart[off];
                #pragma unroll
                for (int w = 1; w < 8; w++) s += Gpart[w * 2112 + off];
                Gb[b * 34 + colb + j] = s;
            }
        }
        __syncthreads();

        // ---- fused pointwise LSTM update ----
        #pragma unroll
        for (int r8 = 0; r8 < 2; r8++) {
            const int e = tid + r8 * 256;
            const int b = e >> 3, j = e & 7;
            const float ig = Gb[b * 34 + j]      + xvv[r8][0];
            const float fg = Gb[b * 34 + 8 + j]  + xvv[r8][1];
            const float gg = Gb[b * 34 + 16 + j] + xvv[r8][2];
            const float og = Gb[b * 34 + 24 + j] + xvv[r8][3];
            const float si = 1.0f / (1.0f + __expf(-ig));
            const float sf = 1.0f / (1.0f + __expf(-fg));
            const float so = 1.0f / (1.0f + __expf(-og));
            const float tg = tanhf(gg);
            const float cn = sf * Cs[e] + si * tg;
            const float hn = so * tanhf(cn);
            Cs[e] = cn;
            const int hc = nb * 8 + j;
            __stcg(out_t + (size_t)b * HH + hc, hn);
            __stcg(hr_nxt + (size_t)b * HH + hc, __uint_as_float(rna_tf32(hn)));
            if (t == TT - 1) {
                hf[(size_t)b * HH + hc] = hn;
                cf[(size_t)b * HH + hc] = cn;
            }
        }

        // ---- grid-wide barrier ----
        __syncthreads();
        if (tid == 0) {
            __threadfence();
            const unsigned target = (unsigned)(t + 1) * GRID;
            atomicAdd(&g_bar, 1u);
            while (*(volatile unsigned*)&g_bar < target) { }
            __threadfence();
        }
        __syncthreads();
    }
}

// ---------------------------------------------------------------------------
extern "C" void kernel_launch(void* const* d_in, const int* in_sizes, int n_in,
                              void* d_out, int out_size)
{
    const float* input = (const float*)d_in[0];
    const float* h0    = (const float*)d_in[1];
    const float* c0    = (const float*)d_in[2];
    const float* w_ih  = (const float*)d_in[3];
    const float* w_hh  = (const float*)d_in[4];
    const float* b_ih  = (const float*)d_in[5];
    const float* b_hh  = (const float*)d_in[6];

    float* outputs = (float*)d_out;                 // [T, B, H]
    float* hf = outputs + (size_t)TT * BB * HH;
    float* cf = hf + (size_t)BB * HH;

    float* xg = nullptr;
    cudaGetSymbolAddress((void**)&xg, g_xg);

    cudaFuncSetAttribute(gemm_mma,
                         cudaFuncAttributeMaxDynamicSharedMemorySize,
                         GEMM_SMEM);
    cudaFuncSetAttribute(lstm_persist,
                         cudaFuncAttributeMaxDynamicSharedMemorySize,
                         (int)(SMEM_FLOATS * sizeof(float)));

    cvt_tf32<<<T_F4 / 256, 256>>>(input, w_ih);
    gemm_mma<<<dim3(32, 256), 256, GEMM_SMEM>>>(b_ih, b_hh, xg);
    prep<<<64, 256>>>(h0);
    lstm_persist<<<GRID, 256, SMEM_FLOATS * sizeof(float)>>>(xg, c0, w_hh,
                                                             outputs, hf, cf);
}

// round 15
// speedup vs baseline: 3.3340x; 1.0026x over previous
#include <cuda_runtime.h>
#include <math.h>
#include <stdint.h>

#define TT   512
#define BB   64
#define II   1024
#define HH   1024
#define G4   4096      // 4*H
#define GRID 128       // persistent CTAs for recurrence

typedef unsigned long long ull;

// Static device scratch (no runtime alloc)
__device__ float g_xg[(size_t)TT * BB * G4];     // x_gates [T, B, 4H]
__device__ float g_a[(size_t)TT * BB * II];      // tf32-rounded input  [32768, 1024]
__device__ float g_b[(size_t)G4 * II];           // tf32-rounded w_ih   [4096, 1024]
__device__ float g_hr[2][BB * HH];               // rna-rounded h ping-pong [b][h]
__device__ unsigned g_bar;

__device__ __forceinline__ void cp16(uint32_t dst_smem, const void* src) {
    asm volatile("cp.async.cg.shared.global [%0], [%1], 16;"
                 :: "r"(dst_smem), "l"(src));
}
__device__ __forceinline__ uint32_t rna_tf32(float x) {
    uint32_t r; asm("cvt.rna.tf32.f32 %0, %1;" : "=r"(r) : "f"(x)); return r;
}
__device__ __forceinline__ void mma_tf32(float* c, const uint32_t* a,
                                         const uint32_t* b) {
    asm("mma.sync.aligned.m16n8k8.row.col.f32.tf32.tf32.f32 "
        "{%0,%1,%2,%3}, {%4,%5,%6,%7}, {%8,%9}, {%0,%1,%2,%3};"
        : "+f"(c[0]), "+f"(c[1]), "+f"(c[2]), "+f"(c[3])
        : "r"(a[0]), "r"(a[1]), "r"(a[2]), "r"(a[3]), "r"(b[0]), "r"(b[1]));
}
// fast tanh: clamped exp form; |err| ~1e-6, safe at extremes.
__device__ __forceinline__ float ftanh(float x) {
    const float xc = fminf(fmaxf(x, -15.0f), 15.0f);
    const float e = __expf(2.0f * xc);
    return __fdividef(e - 1.0f, e + 1.0f);
}
__device__ __forceinline__ float fsigm(float x) {
    const float e = __expf(-fmaxf(x, -80.0f));   // e <= e^80 << 2^126
    return __fdividef(1.0f, 1.0f + e);
}

// ---------------------------------------------------------------------------
// cvt pass: round input + w_ih to tf32 (rna) into g_a / g_b.
// ---------------------------------------------------------------------------
#define A_F4 8388608   // input float4 count
#define T_F4 9437184   // total float4 count
__global__ __launch_bounds__(256)
void cvt_tf32(const float* __restrict__ in, const float* __restrict__ wih)
{
    const int idx = blockIdx.x * 256 + threadIdx.x;
    const float4* src; float* dst; int i4;
    if (idx < A_F4) { src = (const float4*)in;  dst = g_a; i4 = idx; }
    else            { src = (const float4*)wih; dst = g_b; i4 = idx - A_F4; }
    float4 v = src[i4];
    uint4 o;
    o.x = rna_tf32(v.x); o.y = rna_tf32(v.y);
    o.z = rna_tf32(v.z); o.w = rna_tf32(v.w);
    *(uint4*)(dst + (size_t)i4 * 4) = o;
}

// ---------------------------------------------------------------------------
// Phase 1: tf32 mma.sync GEMM (proven in R10/R11/R14).
// ---------------------------------------------------------------------------
#define ATILE 4608
#define GEMM_SMEM (4 * ATILE * 4)

__device__ __forceinline__ void stage_ab(uint32_t sb, int s, const float* ga,
                                         const float* gb_, int kb, int tid)
{
    const uint32_t ab = sb + (uint32_t)(s * ATILE) * 4;
    const uint32_t bbse = sb + (uint32_t)((2 + s) * ATILE) * 4;
    #pragma unroll
    for (int r = 0; r < 4; r++) {
        const int id = tid + r * 256;
        const int row = id >> 3, k = (id & 7) * 4;
        cp16(ab + (uint32_t)(row * 36 + k) * 4,
             ga + (size_t)row * II + kb * 32 + k);
    }
    #pragma unroll
    for (int r = 0; r < 4; r++) {
        const int id = tid + r * 256;
        const int row = id >> 3, k = (id & 7) * 4;
        cp16(bbse + (uint32_t)(row * 36 + k) * 4,
             gb_ + (size_t)row * II + kb * 32 + k);
    }
    asm volatile("cp.async.commit_group;");
}

__global__ __launch_bounds__(256, 2)
void gemm_mma(const float* __restrict__ bih, const float* __restrict__ bhh,
              float* __restrict__ C)
{
    extern __shared__ float sm[];
    const uint32_t sbase = (uint32_t)__cvta_generic_to_shared(sm);

    const int tid = threadIdx.x;
    const int wid = tid >> 5, lid = tid & 31;
    const int wm = wid >> 2, wn = wid & 3;
    const int r = lid >> 2, cq = lid & 3;
    const int n0 = blockIdx.x * 128;
    const int m0 = blockIdx.y * 128;
    const float* ga  = g_a + (size_t)m0 * II;
    const float* gb_ = g_b + (size_t)n0 * II;

    float acc[4][4][4];
    #pragma unroll
    for (int i = 0; i < 4; i++)
        #pragma unroll
        for (int j = 0; j < 4; j++)
            #pragma unroll
            for (int q = 0; q < 4; q++) acc[i][j][q] = 0.0f;

    stage_ab(sbase, 0, ga, gb_, 0, tid);

    for (int kb = 0; kb < 32; kb++) {
        if (kb < 31) {
            stage_ab(sbase, (kb + 1) & 1, ga, gb_, kb + 1, tid);
            asm volatile("cp.async.wait_group 1;");
        } else {
            asm volatile("cp.async.wait_group 0;");
        }
        __syncthreads();

        const uint32_t* Au = (const uint32_t*)(sm + (kb & 1) * ATILE);
        const uint32_t* Bu = (const uint32_t*)(sm + (2 + (kb & 1)) * ATILE);

        #pragma unroll
        for (int ks = 0; ks < 4; ks++) {
            const int k0 = ks * 8;
            uint32_t a[4][4], b[4][2];
            #pragma unroll
            for (int i = 0; i < 4; i++) {
                const int base = (wm * 64 + i * 16 + r) * 36 + k0 + cq;
                a[i][0] = Au[base];
                a[i][1] = Au[base + 8 * 36];
                a[i][2] = Au[base + 4];
                a[i][3] = Au[base + 8 * 36 + 4];
            }
            #pragma unroll
            for (int j = 0; j < 4; j++) {
                const int base = (wn * 32 + j * 8 + r) * 36 + k0 + cq;
                b[j][0] = Bu[base];
                b[j][1] = Bu[base + 4];
            }
            #pragma unroll
            for (int i = 0; i < 4; i++)
                #pragma unroll
                for (int j = 0; j < 4; j++)
                    mma_tf32(acc[i][j], a[i], b[j]);
        }
        __syncthreads();
    }

    #pragma unroll
    for (int j = 0; j < 4; j++) {
        const int n = n0 + wn * 32 + j * 8 + cq * 2;
        const float b0 = __ldg(bih + n)     + __ldg(bhh + n);
        const float b1 = __ldg(bih + n + 1) + __ldg(bhh + n + 1);
        #pragma unroll
        for (int i = 0; i < 4; i++) {
            const int m = m0 + wm * 64 + i * 16 + r;
            float2 lo = { acc[i][j][0] + b0, acc[i][j][1] + b1 };
            float2 hi = { acc[i][j][2] + b0, acc[i][j][3] + b1 };
            *(float2*)(C + (size_t)m * G4 + n)       = lo;
            *(float2*)(C + (size_t)(m + 8) * G4 + n) = hi;
        }
    }
}

// ---------------------------------------------------------------------------
// prep: rna-round h0 -> g_hr[0] and reset grid barrier.
// ---------------------------------------------------------------------------
__global__ __launch_bounds__(256)
void prep(const float* __restrict__ h0)
{
    const int i4 = blockIdx.x * 256 + threadIdx.x;   // 0..16383
    float4 v = ((const float4*)h0)[i4];
    uint4 o;
    o.x = rna_tf32(v.x); o.y = rna_tf32(v.y);
    o.z = rna_tf32(v.z); o.w = rna_tf32(v.w);
    *(uint4*)(g_hr[0] + (size_t)i4 * 4) = o;
    if (i4 == 0) g_bar = 0;
}

// ---------------------------------------------------------------------------
// Persistent recurrence, tensorized + split-K-across-warps (R14 base) with:
//  - single __syncthreads per k-chunk (bottom syncs removed; one sync after
//    the k-loop protects the Gpart/staging-buffer alias)
//  - xg prefetch for step t+1 issued BEFORE the grid barrier
//  - fast tanh/sigmoid in the pointwise
// ---------------------------------------------------------------------------
#define WS_STRIDE 1028
#define HS_OFF 32896
#define HS_STG (64 * 132)
#define GB_OFF (HS_OFF + 2 * HS_STG)
#define CS_OFF (GB_OFF + 64 * 34)
#define SMEM_FLOATS (CS_OFF + 512)

__global__ __launch_bounds__(256, 1)
void lstm_persist(const float* __restrict__ xg, const float* c0,
                  const float* __restrict__ Whh,
                  float* out, float* hf, float* cf)
{
    extern __shared__ float sm[];
    float* Ws = sm;
    float* Gpart = sm + HS_OFF;            // aliases Hs after K-loop
    float* Gb = sm + GB_OFF;
    float* Cs = sm + CS_OFF;
    const uint32_t sbase = (uint32_t)__cvta_generic_to_shared(sm);
    const uint32_t hsb   = sbase + HS_OFF * 4;

    const int tid = threadIdx.x;
    const int nb  = blockIdx.x;            // 0..127

    // ---- load W slice (32 gate rows x 1024), rna-rounded -> Ws[col][k] ----
    {
        const int col = tid >> 3;          // 0..31 local gate col
        const int l8  = tid & 7;
        const int grow = (col >> 3) * HH + nb * 8 + (col & 7);
        const float* wr = Whh + (size_t)grow * HH;
        for (int k0 = l8 * 4; k0 < II; k0 += 32) {
            float4 v = *(const float4*)(wr + k0);
            uint4 o;
            o.x = rna_tf32(v.x); o.y = rna_tf32(v.y);
            o.z = rna_tf32(v.z); o.w = rna_tf32(v.w);
            *(uint4*)(Ws + col * WS_STRIDE + k0) = o;
        }
    }
    #pragma unroll
    for (int r8 = 0; r8 < 2; r8++) {
        const int e = tid + r8 * 256;
        const int b = e >> 3, j = e & 7;
        Cs[e] = c0[(size_t)b * HH + nb * 8 + j];
    }
    __syncthreads();

    const int wid = tid >> 5, lid = tid & 31;
    const int r  = lid >> 2, cq = lid & 3;
    const int kw = wid * 16;               // warp's k-offset within chunk

    // ---- prefetch xg for step 0 ----
    float xvv[2][4];
    #pragma unroll
    for (int r8 = 0; r8 < 2; r8++) {
        const int e = tid + r8 * 256;
        const int b = e >> 3, j = e & 7;
        #pragma unroll
        for (int s = 0; s < 4; s++)
            xvv[r8][s] = __ldg(xg + (size_t)b * G4 + s * HH + nb * 8 + j);
    }

    for (int t = 0; t < TT; t++) {
        const float* hr_cur = g_hr[t & 1];
        float*       hr_nxt = g_hr[(t + 1) & 1];
        float*       out_t  = out + (size_t)t * BB * HH;

        // ---- prologue: stage k-chunk 0 ----
        #pragma unroll
        for (int r8 = 0; r8 < 8; r8++) {
            const int id = tid + r8 * 256;
            const int b = id >> 5, q = id & 31;
            cp16(hsb + (uint32_t)(b * 132 + q * 4) * 4,
                 hr_cur + (size_t)b * HH + q * 4);
        }
        asm volatile("cp.async.commit_group;");

        float acc[4][4][4];
        #pragma unroll
        for (int i = 0; i < 4; i++)
            #pragma unroll
            for (int j = 0; j < 4; j++)
                #pragma unroll
                for (int q = 0; q < 4; q++) acc[i][j][q] = 0.0f;

        for (int ch = 0; ch < 8; ch++) {
            asm volatile("cp.async.wait_group 0;");
            __syncthreads();   // chunk ch visible; all warps past mma(ch-1)

            if (ch < 7) {      // buffer (ch+1)&1 last read at ch-1 -> safe
                const uint32_t db = hsb + (uint32_t)(((ch + 1) & 1) * HS_STG) * 4;
                const float* sb = hr_cur + (ch + 1) * 128;
                #pragma unroll
                for (int r8 = 0; r8 < 8; r8++) {
                    const int id = tid + r8 * 256;
                    const int b = id >> 5, q = id & 31;
                    cp16(db + (uint32_t)(b * 132 + q * 4) * 4,
                         sb + (size_t)b * HH + q * 4);
                }
                asm volatile("cp.async.commit_group;");
            }

            const uint32_t* Hu = (const uint32_t*)(sm + HS_OFF + (ch & 1) * HS_STG);
            const uint32_t* Wu = (const uint32_t*)Ws;
            const int kglob = ch * 128 + kw;

            #pragma unroll
            for (int kt2 = 0; kt2 < 2; kt2++) {
                const int kl = kw + kt2 * 8;       // within chunk
                const int kg = kglob + kt2 * 8;    // global k
                uint32_t b_[4][2];
                #pragma unroll
                for (int nt = 0; nt < 4; nt++) {
                    const int bbase = (nt * 8 + r) * WS_STRIDE + kg + cq;
                    b_[nt][0] = Wu[bbase];
                    b_[nt][1] = Wu[bbase + 4];
                }
                #pragma unroll
                for (int mt = 0; mt < 4; mt++) {
                    uint32_t a[4];
                    const int abase = (mt * 16 + r) * 132 + kl + cq;
                    a[0] = Hu[abase];
                    a[1] = Hu[abase + 8 * 132];
                    a[2] = Hu[abase + 4];
                    a[3] = Hu[abase + 8 * 132 + 4];
                    #pragma unroll
                    for (int nt = 0; nt < 4; nt++)
                        mma_tf32(acc[mt][nt], a, b_[nt]);
                }
            }
            // no bottom sync: next iteration's top sync orders buffer reuse
        }
        __syncthreads();       // all mma done before Gpart alias writes

        // ---- write per-warp partials to Gpart[w] (aliases Hs) ----
        {
            float* gp = Gpart + wid * 2112;
            #pragma unroll
            for (int mt = 0; mt < 4; mt++)
                #pragma unroll
                for (int nt = 0; nt < 4; nt++) {
                    const int row = mt * 16 + r;
                    const int col = nt * 8 + cq * 2;
                    gp[row * 33 + col]           = acc[mt][nt][0];
                    gp[row * 33 + col + 1]       = acc[mt][nt][1];
                    gp[(row + 8) * 33 + col]     = acc[mt][nt][2];
                    gp[(row + 8) * 33 + col + 1] = acc[mt][nt][3];
                }
        }
        __syncthreads();

        // ---- 8-way reduction -> Gb[b][col] (conflict-free mapping) ----
        {
            const int b = tid >> 2;
            const int colb = (tid & 3) * 8;
            #pragma unroll
            for (int j = 0; j < 8; j++) {
                const int off = b * 33 + colb + j;
                float s = Gpart[off];
                #pragma unroll
                for (int w = 1; w < 8; w++) s += Gpart[w * 2112 + off];
                Gb[b * 34 + colb + j] = s;
            }
        }
        __syncthreads();

        // ---- fused pointwise LSTM update (fast transcendentals) ----
        #pragma unroll
        for (int r8 = 0; r8 < 2; r8++) {
            const int e = tid + r8 * 256;
            const int b = e >> 3, j = e & 7;
            const float ig = Gb[b * 34 + j]      + xvv[r8][0];
            const float fg = Gb[b * 34 + 8 + j]  + xvv[r8][1];
            const float gg = Gb[b * 34 + 16 + j] + xvv[r8][2];
            const float og = Gb[b * 34 + 24 + j] + xvv[r8][3];
            const float si = fsigm(ig);
            const float sf = fsigm(fg);
            const float so = fsigm(og);
            const float tg = ftanh(gg);
            const float cn = sf * Cs[e] + si * tg;
            const float hn = so * ftanh(cn);
            Cs[e] = cn;
            const int hc = nb * 8 + j;
            __stcg(out_t + (size_t)b * HH + hc, hn);
            __stcg(hr_nxt + (size_t)b * HH + hc, __uint_as_float(rna_tf32(hn)));
            if (t == TT - 1) {
                hf[(size_t)b * HH + hc] = hn;
                cf[(size_t)b * HH + hc] = cn;
            }
        }

        // ---- prefetch xg for step t+1 (latency hides under barrier) ----
        if (t + 1 < TT) {
            const float* xgn = xg + (size_t)(t + 1) * BB * G4;
            #pragma unroll
            for (int r8 = 0; r8 < 2; r8++) {
                const int e = tid + r8 * 256;
                const int b = e >> 3, j = e & 7;
                #pragma unroll
                for (int s = 0; s < 4; s++)
                    xvv[r8][s] = __ldg(xgn + (size_t)b * G4 + s * HH + nb * 8 + j);
            }
        }

        // ---- grid-wide barrier ----
        __syncthreads();
        if (tid == 0) {
            __threadfence();
            const unsigned target = (unsigned)(t + 1) * GRID;
            atomicAdd(&g_bar, 1u);
            while (*(volatile unsigned*)&g_bar < target) { }
            __threadfence();
        }
        __syncthreads();
    }
}

// ---------------------------------------------------------------------------
extern "C" void kernel_launch(void* const* d_in, const int* in_sizes, int n_in,
                              void* d_out, int out_size)
{
    const float* input = (const float*)d_in[0];
    const float* h0    = (const float*)d_in[1];
    const float* c0    = (const float*)d_in[2];
    const float* w_ih  = (const float*)d_in[3];
    const float* w_hh  = (const float*)d_in[4];
    const float* b_ih  = (const float*)d_in[5];
    const float* b_hh  = (const float*)d_in[6];

    float* outputs = (float*)d_out;                 // [T, B, H]
    float* hf = outputs + (size_t)TT * BB * HH;
    float* cf = hf + (size_t)BB * HH;

    float* xg = nullptr;
    cudaGetSymbolAddress((void**)&xg, g_xg);

    cudaFuncSetAttribute(gemm_mma,
                         cudaFuncAttributeMaxDynamicSharedMemorySize,
                         GEMM_SMEM);
    cudaFuncSetAttribute(lstm_persist,
                         cudaFuncAttributeMaxDynamicSharedMemorySize,
                         (int)(SMEM_FLOATS * sizeof(float)));

    cvt_tf32<<<T_F4 / 256, 256>>>(input, w_ih);
    gemm_mma<<<dim3(32, 256), 256, GEMM_SMEM>>>(b_ih, b_hh, xg);
    prep<<<64, 256>>>(h0);
    lstm_persist<<<GRID, 256, SMEM_FLOATS * sizeof(float)>>>(xg, c0, w_hh,
                                                             outputs, hf, cf);
}